// round 7
// baseline (speedup 1.0000x reference)
#include <cuda_runtime.h>

typedef unsigned long long ULL;

__device__ __forceinline__ void fma2(ULL& d, ULL a, ULL b) {
    asm("fma.rn.f32x2 %0, %1, %2, %0;" : "+l"(d) : "l"(a), "l"(b));
}
__device__ __forceinline__ ULL f2add(ULL a, ULL b) {
    ULL d;
    asm("add.rn.f32x2 %0, %1, %2;" : "=l"(d) : "l"(a), "l"(b));
    return d;
}
__device__ __forceinline__ float f2sum(ULL v) {
    float x, y;
    asm("mov.b64 {%0,%1}, %2;" : "=f"(x), "=f"(y) : "l"(v));
    return x + y;
}
__device__ __forceinline__ float sigf(float x) { return 1.f / (1.f + expf(-x)); }

// ---------------- scratch (static device buffers; no allocation) -------------
__device__ float g_x[32768 * 256];          // embedded input
__device__ float g_xg[(size_t)32768 * 2048];// input-proj gates buffer (reused per layer)
__device__ float g_out0[32768 * 512];       // layer0 output
__device__ float g_out1[32768 * 512];       // layer1 output
__device__ float g_h[2 * 2 * 128 * 256];    // h ping-pong [ping][dir][b][k]
__device__ float g_feats[(size_t)32768 * 22];
__device__ float g_nll[128];

// ---------------- embedding gather ----------------
__global__ void embed_k(const float* __restrict__ emb, const int* __restrict__ words) {
    int idx = blockIdx.x * 256 + threadIdx.x;
    int i = idx >> 8, e = idx & 255;
    int w = words[i];
    g_x[idx] = emb[(size_t)w * 256 + e];
}

// ---------------- input-projection GEMM (unchanged, passing) -----------------
template <int K>
__global__ void __launch_bounds__(256) gemm_xg_k(const float* __restrict__ W,
                                                 const float* __restrict__ bi,
                                                 const float* __restrict__ bh) {
    const float* A = (K == 256) ? g_x : g_out0;
    __shared__ float As[2][128][18];
    __shared__ float Ws[2][64][18];

    int tid = threadIdx.x;
    int ty = tid >> 4, tx = tid & 15;
    const float* Ab = A + (size_t)blockIdx.y * 128 * K;
    const float* Wb = W + (size_t)blockIdx.x * 64 * K;

    int arow = tid >> 1, acol = (tid & 1) * 8;
    int wrow = tid >> 2, wcol = (tid & 3) * 4;

    float4 a0, a1, w0;
    a0 = *(const float4*)(Ab + arow * K + acol);
    a1 = *(const float4*)(Ab + arow * K + acol + 4);
    w0 = *(const float4*)(Wb + wrow * K + wcol);
    *(float2*)&As[0][arow][acol + 0] = make_float2(a0.x, a0.y);
    *(float2*)&As[0][arow][acol + 2] = make_float2(a0.z, a0.w);
    *(float2*)&As[0][arow][acol + 4] = make_float2(a1.x, a1.y);
    *(float2*)&As[0][arow][acol + 6] = make_float2(a1.z, a1.w);
    *(float2*)&Ws[0][wrow][wcol + 0] = make_float2(w0.x, w0.y);
    *(float2*)&Ws[0][wrow][wcol + 2] = make_float2(w0.z, w0.w);
    __syncthreads();

    ULL acc[8][4] = {};
    const int NC = K / 16;

    for (int c = 0; c < NC; ++c) {
        int buf = c & 1;
        if (c + 1 < NC) {
            const float* Ap = Ab + arow * K + (c + 1) * 16 + acol;
            a0 = *(const float4*)(Ap);
            a1 = *(const float4*)(Ap + 4);
            w0 = *(const float4*)(Wb + wrow * K + (c + 1) * 16 + wcol);
        }
#pragma unroll
        for (int kp = 0; kp < 8; ++kp) {
            ULL av[8], wv[4];
#pragma unroll
            for (int i = 0; i < 8; ++i) av[i] = *(const ULL*)&As[buf][ty * 8 + i][kp * 2];
#pragma unroll
            for (int j = 0; j < 4; ++j) wv[j] = *(const ULL*)&Ws[buf][tx + j * 16][kp * 2];
#pragma unroll
            for (int i = 0; i < 8; ++i)
#pragma unroll
                for (int j = 0; j < 4; ++j) fma2(acc[i][j], av[i], wv[j]);
        }
        if (c + 1 < NC) {
            int nb = buf ^ 1;
            *(float2*)&As[nb][arow][acol + 0] = make_float2(a0.x, a0.y);
            *(float2*)&As[nb][arow][acol + 2] = make_float2(a0.z, a0.w);
            *(float2*)&As[nb][arow][acol + 4] = make_float2(a1.x, a1.y);
            *(float2*)&As[nb][arow][acol + 6] = make_float2(a1.z, a1.w);
            *(float2*)&Ws[nb][wrow][wcol + 0] = make_float2(w0.x, w0.y);
            *(float2*)&Ws[nb][wrow][wcol + 2] = make_float2(w0.z, w0.w);
            __syncthreads();
        }
    }

#pragma unroll
    for (int i = 0; i < 8; ++i) {
        size_t m = (size_t)blockIdx.y * 128 + ty * 8 + i;
#pragma unroll
        for (int j = 0; j < 4; ++j) {
            int n = blockIdx.x * 64 + tx + j * 16;
            g_xg[m * 2048 + n] = f2sum(acc[i][j]) + bi[n] + bh[n];
        }
    }
}

// ---------------- zero h pings ----------------
__global__ void init_hc() {
    int i = blockIdx.x * 256 + threadIdx.x;   // 512*256 = 131072 = all of g_h
    g_h[i] = 0.f;
}

// ---------------- persistent BiLSTM layer v4 (cluster-8 sync) ------------------
// 128 blocks = 16 clusters of 8. Cluster = one (dir,bch) h-exchange group:
//   uch = bx&7 (32 units), dir = (bx>>3)&1, bch = bx>>4 (16 batches).
// 512 threads: wg = tid>>7 splits K 4 ways (64 k each); wtid = tid&127:
//   u2 = wtid&15 (units u2, u2+16), bg = wtid>>4 (8 groups x 2 batches).
// W_hh slice (128 rows x 256) staged once in smem (stride 260 = 16B aligned);
// c in registers; compute uses LDS.128; barrier = barrier.cluster arrive/wait
// with next step's xg prefetch issued between arrive and wait.
#define LSTM_SMEM (144 * 260 * 4 + 4 * 128 * 17 * 8)
__global__ void __launch_bounds__(512, 1) lstm_persist(const float* __restrict__ whh, int layer) {
    extern __shared__ float sm[];
    float* ws = sm;                       // [128][260] rows: g*32 + u_local
    float* hs = sm + 128 * 260;           // [16][260]
    ULL* part = (ULL*)(sm + 144 * 260);   // [4 wg][128 wtid][17]

    int bx = blockIdx.x;
    int uch = bx & 7, dir = (bx >> 3) & 1, bch = bx >> 4;
    int tid = threadIdx.x;
    int wg = tid >> 7, wtid = tid & 127;
    int u2 = wtid & 15, bg = wtid >> 4;

    // epilogue mapping: one (batch, unit) cell per thread
    int u_l = tid & 31, b_l = tid >> 5;               // u 0..31, b 0..15
    int b_g = bch * 16 + b_l, u_g = uch * 32 + u_l;
    int src_wtid = (b_l >> 1) * 16 + (u_l & 15);
    int cellofs = (u_l >> 4) * 2 + (b_l & 1);

    // stage W_hh slice once: 128 rows x 256 k
    const float* wb = whh + (size_t)dir * 1024 * 256;
#pragma unroll 4
    for (int r = 0; r < 32; ++r) {
        int q = r * 512 + tid;
        int wrow = q >> 7, cc = q & 127;
        int g = wrow >> 5, uw = wrow & 31;
        *(float2*)&ws[wrow * 260 + cc * 2] =
            *(const float2*)&wb[(size_t)(g * 256 + uch * 32 + uw) * 256 + cc * 2];
    }

    float creg = 0.f;
    float* ob = layer ? g_out1 : g_out0;
    const int kbase = wg * 64;

    // prefetch xg for t = 0
    float xg[4];
    {
        int td0 = dir ? 255 : 0;
        size_t xb = ((size_t)b_g * 256 + td0) * 2048 + dir * 1024 + u_g;
        xg[0] = __ldcg(&g_xg[xb]);
        xg[1] = __ldcg(&g_xg[xb + 256]);
        xg[2] = __ldcg(&g_xg[xb + 512]);
        xg[3] = __ldcg(&g_xg[xb + 768]);
    }

    for (int t = 0; t < 256; ++t) {
        int td = dir ? 255 - t : t;
        const float* hin = g_h + (t & 1) * (2 * 128 * 256);
        float* hout = g_h + ((t & 1) ^ 1) * (2 * 128 * 256);

        // stage h_{t-1}: 16 batches x 256 k = 2048 float2, 4 per thread
        const float* hb = hin + (dir * 128 + bch * 16) * 256;
#pragma unroll
        for (int r = 0; r < 4; ++r) {
            int q = r * 512 + tid;
            int row = q >> 7, cc = q & 127;
            *(float2*)&hs[row * 260 + cc * 2] = __ldcg((const float2*)&hb[row * 256 + cc * 2]);
        }
        __syncthreads();

        // MMA: acc[g][uo][jb], 4 k per iteration via LDS.128
        ULL acc[16] = {};
#pragma unroll
        for (int kq = 0; kq < 16; ++kq) {
            ulonglong2 hv[2], wv[8];
#pragma unroll
            for (int jb = 0; jb < 2; ++jb)
                hv[jb] = *(const ulonglong2*)&hs[(bg * 2 + jb) * 260 + kbase + kq * 4];
#pragma unroll
            for (int g = 0; g < 4; ++g)
#pragma unroll
                for (int uo = 0; uo < 2; ++uo)
                    wv[g * 2 + uo] = *(const ulonglong2*)&ws[(g * 32 + uo * 16 + u2) * 260 + kbase + kq * 4];
#pragma unroll
            for (int g = 0; g < 4; ++g)
#pragma unroll
                for (int uo = 0; uo < 2; ++uo)
#pragma unroll
                    for (int jb = 0; jb < 2; ++jb) {
                        fma2(acc[g * 4 + uo * 2 + jb], hv[jb].x, wv[g * 2 + uo].x);
                        fma2(acc[g * 4 + uo * 2 + jb], hv[jb].y, wv[g * 2 + uo].y);
                    }
        }

        {
            ULL* pp = &part[(wg * 128 + wtid) * 17];
#pragma unroll
            for (int i = 0; i < 16; ++i) pp[i] = acc[i];
        }
        __syncthreads();

        // epilogue: one cell per thread
        {
            float gv[4];
#pragma unroll
            for (int g = 0; g < 4; ++g) {
                ULL s = part[src_wtid * 17 + g * 4 + cellofs];
#pragma unroll
                for (int w = 1; w < 4; ++w)
                    s = f2add(s, part[(w * 128 + src_wtid) * 17 + g * 4 + cellofs]);
                gv[g] = f2sum(s) + xg[g];
            }
            float cn = sigf(gv[1]) * creg + sigf(gv[0]) * tanhf(gv[2]);
            float hn = sigf(gv[3]) * tanhf(cn);
            creg = cn;
            hout[(dir * 128 + b_g) * 256 + u_g] = hn;
            ob[((size_t)b_g * 256 + td) * 512 + dir * 256 + u_g] = hn;
        }

        // cluster barrier (release on arrive / acquire on wait orders the h
        // global stores within the cluster). Prefetch next xg inside the wait.
        asm volatile("barrier.cluster.arrive.aligned;" ::: "memory");
        if (t + 1 < 256) {
            int td2 = dir ? 255 - (t + 1) : t + 1;
            size_t xb = ((size_t)b_g * 256 + td2) * 2048 + dir * 1024 + u_g;
            xg[0] = __ldcg(&g_xg[xb]);
            xg[1] = __ldcg(&g_xg[xb + 256]);
            xg[2] = __ldcg(&g_xg[xb + 512]);
            xg[3] = __ldcg(&g_xg[xb + 768]);
        }
        asm volatile("barrier.cluster.wait.aligned;" ::: "memory");
    }
}

// ---------------- LayerNorm + output projection -------------------------------
__global__ void __launch_bounds__(128) lnfeats(const float* __restrict__ lng,
                                               const float* __restrict__ lnb,
                                               const float* __restrict__ wo,
                                               const float* __restrict__ bo) {
    __shared__ float row[512];
    __shared__ float red[10];
    int i = blockIdx.x, tid = threadIdx.x;
    float4 v = *(const float4*)&g_out1[(size_t)i * 512 + tid * 4];
    float s = v.x + v.y + v.z + v.w;
    float q = v.x * v.x + v.y * v.y + v.z * v.z + v.w * v.w;
#pragma unroll
    for (int o = 16; o; o >>= 1) {
        s += __shfl_xor_sync(0xffffffffu, s, o);
        q += __shfl_xor_sync(0xffffffffu, q, o);
    }
    int wid = tid >> 5, lane = tid & 31;
    if (!lane) { red[wid] = s; red[4 + wid] = q; }
    __syncthreads();
    if (!tid) {
        float S = red[0] + red[1] + red[2] + red[3];
        float Q = red[4] + red[5] + red[6] + red[7];
        float mu = S / 512.f;
        float var = Q / 512.f - mu * mu;
        red[8] = mu;
        red[9] = rsqrtf(var + 1e-5f);
    }
    __syncthreads();
    float mu = red[8], rs = red[9];
    int k = tid * 4;
    row[k + 0] = (v.x - mu) * rs * lng[k + 0] + lnb[k + 0];
    row[k + 1] = (v.y - mu) * rs * lng[k + 1] + lnb[k + 1];
    row[k + 2] = (v.z - mu) * rs * lng[k + 2] + lnb[k + 2];
    row[k + 3] = (v.w - mu) * rs * lng[k + 3] + lnb[k + 3];
    __syncthreads();
    for (int o = wid; o < 22; o += 4) {
        float a = 0.f;
        const float* wr = wo + o * 512;
        for (int k2 = lane; k2 < 512; k2 += 32) a += row[k2] * wr[k2];
#pragma unroll
        for (int off = 16; off; off >>= 1) a += __shfl_xor_sync(0xffffffffu, a, off);
        if (!lane) g_feats[(size_t)i * 22 + o] = a + bo[o];
    }
}

// ---------------- CRF forward + scores (one warp per batch) -------------------
__global__ void crf_k(const float* __restrict__ trans, const int* __restrict__ mask,
                      const int* __restrict__ tags) {
    __shared__ float tr[484];
    __shared__ float alpha[22];
    int b = blockIdx.x, j = threadIdx.x;
    for (int q = j; q < 484; q += 32) tr[q] = trans[q];
    const float* Fb = g_feats + (size_t)b * 256 * 22;
    __syncwarp();
    if (j < 22) alpha[j] = tr[20 * 22 + j] + Fb[j];
    __syncwarp();
    for (int t = 1; t < 256; ++t) {
        float aj = 0.f;
        if (j < 22) {
            float m = -1e30f;
#pragma unroll
            for (int i2 = 0; i2 < 22; ++i2) m = fmaxf(m, alpha[i2] + tr[i2 * 22 + j]);
            float sm = 0.f;
#pragma unroll
            for (int i2 = 0; i2 < 22; ++i2) sm += expf(alpha[i2] + tr[i2 * 22 + j] - m);
            aj = m + logf(sm) + Fb[t * 22 + j];
        }
        int mt = mask[b * 256 + t];
        __syncwarp();
        if (j < 22 && mt) alpha[j] = aj;
        __syncwarp();
    }
    float v = (j < 22) ? alpha[j] + tr[j * 22 + 21] : -1e30f;
    float m = v;
#pragma unroll
    for (int off = 16; off; off >>= 1) m = fmaxf(m, __shfl_xor_sync(0xffffffffu, m, off));
    float e = (j < 22) ? expf(v - m) : 0.f;
#pragma unroll
    for (int off = 16; off; off >>= 1) e += __shfl_xor_sync(0xffffffffu, e, off);
    float logZ = m + logf(e);

    const int* tg = tags + (size_t)b * 256;
    const int* mk = mask + b * 256;
    float emit = 0.f, trs = 0.f;
    int cnt = 0;
    for (int t = j; t < 256; t += 32) {
        if (mk[t]) {
            emit += Fb[t * 22 + tg[t]];
            cnt++;
            if (t >= 1) trs += tr[tg[t - 1] * 22 + tg[t]];
        }
    }
#pragma unroll
    for (int off = 16; off; off >>= 1) {
        emit += __shfl_xor_sync(0xffffffffu, emit, off);
        trs += __shfl_xor_sync(0xffffffffu, trs, off);
        cnt += __shfl_xor_sync(0xffffffffu, cnt, off);
    }
    if (!j) {
        trs += tr[20 * 22 + tg[0]];
        trs += tr[tg[cnt - 1] * 22 + 21];
        g_nll[b] = logZ - emit - trs;
    }
}

__global__ void reduce_nll(float* out) {
    int tid = threadIdx.x;  // 128
    float v = g_nll[tid];
#pragma unroll
    for (int off = 16; off; off >>= 1) v += __shfl_xor_sync(0xffffffffu, v, off);
    __shared__ float r[4];
    if (!(tid & 31)) r[tid >> 5] = v;
    __syncthreads();
    if (!tid) out[0] = (r[0] + r[1] + r[2] + r[3]) / 128.f;
}

// ---------------- launcher ----------------
extern "C" void kernel_launch(void* const* d_in, const int* in_sizes, int n_in,
                              void* d_out, int out_size) {
    const float* emb    = (const float*)d_in[0];
    const float* w_ih0  = (const float*)d_in[1];
    const float* w_hh0  = (const float*)d_in[2];
    const float* b_ih0  = (const float*)d_in[3];
    const float* b_hh0  = (const float*)d_in[4];
    const float* w_ih1  = (const float*)d_in[5];
    const float* w_hh1  = (const float*)d_in[6];
    const float* b_ih1  = (const float*)d_in[7];
    const float* b_hh1  = (const float*)d_in[8];
    const float* ln_g   = (const float*)d_in[9];
    const float* ln_b   = (const float*)d_in[10];
    const float* w_out  = (const float*)d_in[11];
    const float* b_out  = (const float*)d_in[12];
    const float* trans  = (const float*)d_in[13];
    const int* words    = (const int*)d_in[14];
    const int* mask     = (const int*)d_in[15];
    const int* tags     = (const int*)d_in[16];
    float* out = (float*)d_out;

    cudaFuncSetAttribute(lstm_persist, cudaFuncAttributeMaxDynamicSharedMemorySize, LSTM_SMEM);

    cudaLaunchConfig_t cfg = {};
    cfg.gridDim = dim3(128, 1, 1);
    cfg.blockDim = dim3(512, 1, 1);
    cfg.dynamicSmemBytes = LSTM_SMEM;
    cfg.stream = 0;
    cudaLaunchAttribute attrs[1];
    attrs[0].id = cudaLaunchAttributeClusterDimension;
    attrs[0].val.clusterDim = {8, 1, 1};
    cfg.attrs = attrs;
    cfg.numAttrs = 1;

    embed_k<<<32768, 256>>>(emb, words);
    gemm_xg_k<256><<<dim3(32, 256), 256>>>(w_ih0, b_ih0, b_hh0);
    init_hc<<<512, 256>>>();
    cudaLaunchKernelEx(&cfg, lstm_persist, w_hh0, 0);
    gemm_xg_k<512><<<dim3(32, 256), 256>>>(w_ih1, b_ih1, b_hh1);
    init_hc<<<512, 256>>>();
    cudaLaunchKernelEx(&cfg, lstm_persist, w_hh1, 1);
    lnfeats<<<32768, 128>>>(ln_g, ln_b, w_out, b_out);
    crf_k<<<128, 32>>>(trans, mask, tags);
    reduce_nll<<<1, 128>>>(out);
}

// round 9
// speedup vs baseline: 2.1968x; 2.1968x over previous
#include <cuda_runtime.h>
#include <cuda_bf16.h>
#include <cstdint>

typedef unsigned long long ULL;

// tcgen05 is an arch-SPECIFIC feature: legal in the sm_103a cubin pass,
// illegal in the generic compute_103 PTX pass the harness also emits.
#if !defined(__CUDA_ARCH__) || defined(__CUDA_ARCH_FEAT_SM103_ALL) || \
    defined(__CUDA_ARCH_FEAT_SM100_ALL) || defined(__CUDA_ARCH_SPECIFIC__) || \
    defined(__CUDA_ARCH_FAMILY_SPECIFIC__)
#define TC_OK 1
#else
#define TC_OK 0
#endif

// ---------------- f32x2 helpers (recurrence) ----------------
__device__ __forceinline__ void fma2(ULL& d, ULL a, ULL b) {
    asm("fma.rn.f32x2 %0, %1, %2, %0;" : "+l"(d) : "l"(a), "l"(b));
}
__device__ __forceinline__ ULL f2add(ULL a, ULL b) {
    ULL d;
    asm("add.rn.f32x2 %0, %1, %2;" : "=l"(d) : "l"(a), "l"(b));
    return d;
}
__device__ __forceinline__ float f2sum(ULL v) {
    float x, y;
    asm("mov.b64 {%0,%1}, %2;" : "=f"(x), "=f"(y) : "l"(v));
    return x + y;
}
__device__ __forceinline__ float sigf(float x) { return 1.f / (1.f + expf(-x)); }

// ---------------- tcgen05 helpers (guarded) ----------------
__device__ __forceinline__ uint32_t smem_u32(const void* p) {
    uint32_t a;
    asm("{ .reg .u64 t; cvta.to.shared.u64 t, %1; cvt.u32.u64 %0, t; }" : "=r"(a) : "l"(p));
    return a;
}
#define SW128(o) ((o) ^ (((o) >> 3) & 0x70))
static constexpr uint64_t DESC_BASE_SW128 =
    (uint64_t(2) << 61) | (uint64_t(1) << 46) | (uint64_t(64) << 32) | (uint64_t(1) << 16);
#define MKDESC(a) (DESC_BASE_SW128 | ((uint64_t)((a) >> 4) & 0x3FFF))

#if TC_OK
__device__ __forceinline__ uint32_t elect1() {
    uint32_t p;
    asm volatile("{\n\t.reg .pred p;\n\telect.sync _|p, 0xFFFFFFFF;\n\tselp.b32 %0, 1, 0, p;\n\t}" : "=r"(p));
    return p;
}
#define MBAR_INIT(m, c) asm volatile("mbarrier.init.shared.b64 [%0], %1;" :: "r"(m), "r"(c) : "memory")
#define MBAR_INVAL(m) asm volatile("mbarrier.inval.shared.b64 [%0];" :: "r"(m) : "memory")
#define MBAR_WAIT(m, ph) do { \
    uint32_t _m = (m), _p = (ph), _d; \
    asm volatile("{\n\t.reg .pred p;\n\tmbarrier.try_wait.parity.acquire.cta.shared::cta.b64 p, [%1], %2;\n\tselp.b32 %0,1,0,p;\n\t}" \
        : "=r"(_d) : "r"(_m), "r"(_p) : "memory"); \
    if (!_d) { asm volatile("{\n\t.reg .pred P1;\n\tWL%=:\n\tmbarrier.try_wait.parity.acquire.cta.shared::cta.b64 P1, [%0], %1, 0x989680;\n\t@P1 bra.uni WD%=;\n\tbra.uni WL%=;\n\tWD%=:\n\t}" :: "r"(_m), "r"(_p) : "memory"); } \
} while (0)
#define TC_ALLOC(sa, n)  asm volatile("tcgen05.alloc.cta_group::1.sync.aligned.shared::cta.b32 [%0], %1;" :: "r"(sa), "r"(n) : "memory")
#define TC_RELINQ()      asm volatile("tcgen05.relinquish_alloc_permit.cta_group::1.sync.aligned;")
#define TC_DEALLOC(t, n) asm volatile("tcgen05.dealloc.cta_group::1.sync.aligned.b32 %0, %1;" :: "r"(t), "r"(n))
#define TC_COMMIT(m)     asm volatile("tcgen05.commit.cta_group::1.mbarrier::arrive::one.shared::cluster.b64 [%0];" :: "r"(m) : "memory")
#define TC_WAIT_LD()     asm volatile("tcgen05.wait::ld.sync.aligned;" ::: "memory")
#define TC_FENCE_AFTER() asm volatile("tcgen05.fence::after_thread_sync;" ::: "memory")
#define TC_FENCE_BEFORE() asm volatile("tcgen05.fence::before_thread_sync;" ::: "memory")
#define FENCE_ASYNC()    asm volatile("fence.proxy.async.shared::cta;" ::: "memory")
#define TC_LD_X32(r, a) \
    asm volatile("tcgen05.ld.sync.aligned.32x32b.x32.b32 " \
        "{%0,%1,%2,%3,%4,%5,%6,%7,%8,%9,%10,%11,%12,%13,%14,%15," \
        "%16,%17,%18,%19,%20,%21,%22,%23,%24,%25,%26,%27,%28,%29,%30,%31}, [%32];" \
        : "=r"((r)[0]),"=r"((r)[1]),"=r"((r)[2]),"=r"((r)[3]),"=r"((r)[4]),"=r"((r)[5]),"=r"((r)[6]),"=r"((r)[7]), \
          "=r"((r)[8]),"=r"((r)[9]),"=r"((r)[10]),"=r"((r)[11]),"=r"((r)[12]),"=r"((r)[13]),"=r"((r)[14]),"=r"((r)[15]), \
          "=r"((r)[16]),"=r"((r)[17]),"=r"((r)[18]),"=r"((r)[19]),"=r"((r)[20]),"=r"((r)[21]),"=r"((r)[22]),"=r"((r)[23]), \
          "=r"((r)[24]),"=r"((r)[25]),"=r"((r)[26]),"=r"((r)[27]),"=r"((r)[28]),"=r"((r)[29]),"=r"((r)[30]),"=r"((r)[31]) \
        : "r"(a))
__device__ __forceinline__ void mma_f16_ss(uint32_t d, uint64_t ad, uint64_t bd, uint32_t idesc, uint32_t en) {
    asm volatile(
        "{\n\t.reg .pred p;\n\tsetp.ne.u32 p, %5, 0;\n\t"
        "tcgen05.mma.cta_group::1.kind::f16 [%0], %1, %2, %3, {%4, %4, %4, %4}, p;\n\t}"
        :: "r"(d), "l"(ad), "l"(bd), "r"(idesc), "r"(0u), "r"(en) : "memory");
}
#endif // TC_OK

// M=128, N=128, bf16 x bf16 -> f32
static constexpr uint32_t GEMM_IDESC = (1u << 4) | (1u << 7) | (1u << 10) | (16u << 17) | (8u << 24);

// ---------------- scratch ----------------
__device__ __nv_bfloat16 g_Ah[(size_t)32768 * 512];
__device__ __nv_bfloat16 g_Al[(size_t)32768 * 512];
__device__ __nv_bfloat16 g_Wh[2048 * 512];
__device__ __nv_bfloat16 g_Wl[2048 * 512];
__device__ float g_xg[(size_t)32768 * 2048];
__device__ float g_out0[32768 * 512];
__device__ float g_out1[32768 * 512];
__device__ float g_h[2 * 2 * 128 * 256];
__device__ float g_feats[(size_t)32768 * 22];
__device__ float g_nll[128];
__device__ unsigned g_bar[8];

// ---------------- embedding gather -> bf16 hi/lo (layer0 A, stride 256) ------
__global__ void embed_bf(const float* __restrict__ emb, const int* __restrict__ words) {
    int idx = blockIdx.x * 256 + threadIdx.x;
    int i = idx >> 8, e = idx & 255;
    float x = emb[(size_t)words[i] * 256 + e];
    __nv_bfloat16 h = __float2bfloat16_rn(x);
    g_Ah[idx] = h;
    g_Al[idx] = __float2bfloat16_rn(x - __bfloat162float(h));
}

// ---------------- fp32 -> bf16 hi/lo converters ----------------
__global__ void conv_a1(void) {   // g_out0 [32768][512] -> g_Ah/g_Al stride 512
    size_t idx = (size_t)blockIdx.x * 256 + threadIdx.x;
    float x = g_out0[idx];
    __nv_bfloat16 h = __float2bfloat16_rn(x);
    g_Ah[idx] = h;
    g_Al[idx] = __float2bfloat16_rn(x - __bfloat162float(h));
}
__global__ void conv_w(const float* __restrict__ W) {  // [2048][K] flat
    size_t idx = (size_t)blockIdx.x * 256 + threadIdx.x;
    float x = W[idx];
    __nv_bfloat16 h = __float2bfloat16_rn(x);
    g_Wh[idx] = h;
    g_Wl[idx] = __float2bfloat16_rn(x - __bfloat162float(h));
}

// ---------------- tcgen05 input-projection GEMM -------------------------------
// C[32768][2048] = A[32768][K] * W[2048][K]^T + (bi + bh), via bf16 split:
// D = Ah*Wh + Ah*Wl + Al*Wh accumulated in fp32 TMEM (128 cols).
// CTA tile m128 x n128; K staged in 64-col SW128 chunks.
#define GT_SMEM (1024 + 4 * 16384)
template <int K>
__global__ void __launch_bounds__(256, 2)
gemm_tc(const float* __restrict__ bi, const float* __restrict__ bh) {
#if TC_OK
    extern __shared__ char smx[];
    uint32_t sb = smem_u32(smx);
    const int SM_TM = 0, SM_MB = 8;
    const int SM_AH = 1024, SM_AL = SM_AH + 16384, SM_WH = SM_AL + 16384, SM_WL = SM_WH + 16384;

    int tid = threadIdx.x, wid = tid >> 5, lid = tid & 31;
    int nt = blockIdx.x, mt = blockIdx.y;

    if (wid == 0) {
        TC_ALLOC(sb + SM_TM, 128);
        TC_RELINQ();
    }
    if (tid == 0) MBAR_INIT(sb + SM_MB, 1);
    __syncthreads();
    uint32_t tmem;
    asm volatile("ld.shared.b32 %0, [%1];" : "=r"(tmem) : "r"(sb + SM_TM));

    const int NC = K / 64;
    for (int ci = 0; ci < NC; ++ci) {
        // stage A (hi/lo) and W (hi/lo): 128 rows x 64 bf16 each, SW128 swizzle
#pragma unroll
        for (int i = 0; i < 4; ++i) {
            int idx = i * 256 + tid;
            int r = idx >> 3, c8 = idx & 7;
            uint32_t so = SW128((uint32_t)(r * 128 + c8 * 16));
            size_t ga = (size_t)(mt * 128 + r) * K + ci * 64 + c8 * 8;
            *(uint4*)(smx + SM_AH + so) = *(const uint4*)(g_Ah + ga);
            *(uint4*)(smx + SM_AL + so) = *(const uint4*)(g_Al + ga);
            size_t gw = (size_t)(nt * 128 + r) * K + ci * 64 + c8 * 8;
            *(uint4*)(smx + SM_WH + so) = *(const uint4*)(g_Wh + gw);
            *(uint4*)(smx + SM_WL + so) = *(const uint4*)(g_Wl + gw);
        }
        FENCE_ASYNC();
        __syncthreads();

        if (wid == 0 && elect1()) {
            uint64_t dAh = MKDESC(sb + SM_AH), dAl = MKDESC(sb + SM_AL);
            uint64_t dWh = MKDESC(sb + SM_WH), dWl = MKDESC(sb + SM_WL);
#pragma unroll
            for (int k = 0; k < 4; ++k) {
                uint64_t o = k * 2;
                mma_f16_ss(tmem, dAh + o, dWh + o, GEMM_IDESC, !(ci == 0 && k == 0));
                mma_f16_ss(tmem, dAh + o, dWl + o, GEMM_IDESC, 1u);
                mma_f16_ss(tmem, dAl + o, dWh + o, GEMM_IDESC, 1u);
            }
            TC_COMMIT(sb + SM_MB);
        }
        MBAR_WAIT(sb + SM_MB, (uint32_t)(ci & 1));
        __syncthreads();
    }

    TC_FENCE_AFTER();
    if (wid < 4) {
        int m = mt * 128 + wid * 32 + lid;
#pragma unroll
        for (int nb = 0; nb < 4; ++nb) {
            uint32_t dr[32];
            TC_LD_X32(dr, tmem + nb * 32);
            TC_WAIT_LD();
            int n0 = nt * 128 + nb * 32;
#pragma unroll
            for (int c8 = 0; c8 < 8; ++c8) {
                float4 o;
                int n = n0 + c8 * 4;
                o.x = __uint_as_float(dr[c8 * 4 + 0]) + bi[n + 0] + bh[n + 0];
                o.y = __uint_as_float(dr[c8 * 4 + 1]) + bi[n + 1] + bh[n + 1];
                o.z = __uint_as_float(dr[c8 * 4 + 2]) + bi[n + 2] + bh[n + 2];
                o.w = __uint_as_float(dr[c8 * 4 + 3]) + bi[n + 3] + bh[n + 3];
                *(float4*)&g_xg[(size_t)m * 2048 + n] = o;
            }
        }
    }
    TC_FENCE_BEFORE();
    __syncthreads();
    if (tid == 0) MBAR_INVAL(sb + SM_MB);
    if (wid == 0) TC_DEALLOC(tmem, 128);
#else
    // Correct SIMT fallback for the generic compute_103 PTX pass.
    // Never executed on GB300 (driver picks the exact sm_103a cubin).
    int tid = threadIdx.x;
    int nt = blockIdx.x, mt = blockIdx.y;
    for (int q = tid; q < 128 * 128; q += 256) {
        int mi = q >> 7, ni = q & 127;
        int m = mt * 128 + mi, n = nt * 128 + ni;
        float s = 0.f;
        for (int k = 0; k < K; ++k) {
            float a = __bfloat162float(g_Ah[(size_t)m * K + k]) + __bfloat162float(g_Al[(size_t)m * K + k]);
            float w = __bfloat162float(g_Wh[(size_t)n * K + k]) + __bfloat162float(g_Wl[(size_t)n * K + k]);
            s += a * w;
        }
        g_xg[(size_t)m * 2048 + n] = s + bi[n] + bh[n];
    }
#endif
}

// ---------------- zero h pings + group barriers ----------------
__global__ void init_hc() {
    int i = blockIdx.x * 256 + threadIdx.x;
    g_h[i] = 0.f;
    if (i < 8) g_bar[i] = 0u;
}

// ---------------- persistent BiLSTM layer (round-5 proven version) -----------
#define PERS_SMEM ((64 * 258 + 32 * 258) * 4 + 3 * 128 * 17 * 8)
__global__ void __launch_bounds__(512) lstm_persist(const float* __restrict__ whh, int layer) {
    extern __shared__ float sm[];
    float* ws = sm;                       // [64][258] rows: g*16+u
    float* hs = sm + 64 * 258;            // [32][258]
    ULL* part = (ULL*)(sm + 96 * 258);    // [3][128][17]

    int bx = blockIdx.x;
    int dir = bx & 1, bch = (bx >> 1) & 3, uch = bx >> 3;
    int grp = bx & 7;
    int tid = threadIdx.x;
    int wg = tid >> 7, wtid = tid & 127;
    int u = wtid & 15, bg = wtid >> 4;
    int uu = uch * 16 + u;
    int b0 = bch * 32 + bg * 4;

    const float* wb = whh + (size_t)dir * 1024 * 256;
#pragma unroll 4
    for (int r = 0; r < 16; ++r) {
        int q = r * 512 + tid;
        int wrow = q >> 7, cc = q & 127;
        int gt = wrow >> 4, uw = wrow & 15;
        *(float2*)&ws[wrow * 258 + cc * 2] =
            *(const float2*)&wb[(size_t)(gt * 256 + uch * 16 + uw) * 256 + cc * 2];
    }

    float creg[4] = {0.f, 0.f, 0.f, 0.f};
    float* ob = layer ? g_out1 : g_out0;
    const int kbase = wg * 64;

    for (int t = 0; t < 256; ++t) {
        int td = dir ? 255 - t : t;
        const float* hin = g_h + (t & 1) * (2 * 128 * 256);
        float* hout = g_h + ((t & 1) ^ 1) * (2 * 128 * 256);

        float xg[16];
        if (wg == 0) {
#pragma unroll
            for (int j = 0; j < 4; ++j) {
                size_t xb = ((size_t)(b0 + j) * 256 + td) * 2048 + dir * 1024 + uu;
                xg[j * 4 + 0] = __ldcg(&g_xg[xb]);
                xg[j * 4 + 1] = __ldcg(&g_xg[xb + 256]);
                xg[j * 4 + 2] = __ldcg(&g_xg[xb + 512]);
                xg[j * 4 + 3] = __ldcg(&g_xg[xb + 768]);
            }
        }

        const float* hb = hin + (dir * 128 + bch * 32) * 256;
#pragma unroll
        for (int r = 0; r < 8; ++r) {
            int q = r * 512 + tid;
            int row = q >> 7, cc = q & 127;
            *(float2*)&hs[row * 258 + cc * 2] = __ldcg((const float2*)&hb[row * 256 + cc * 2]);
        }
        __syncthreads();

        ULL acc[4][4] = {};
#pragma unroll 8
        for (int kp = 0; kp < 32; ++kp) {
            ULL hv[4], wv[4];
#pragma unroll
            for (int j = 0; j < 4; ++j)
                hv[j] = *(const ULL*)&hs[(bg * 4 + j) * 258 + kbase + kp * 2];
#pragma unroll
            for (int g = 0; g < 4; ++g)
                wv[g] = *(const ULL*)&ws[(g * 16 + u) * 258 + kbase + kp * 2];
#pragma unroll
            for (int g = 0; g < 4; ++g)
#pragma unroll
                for (int j = 0; j < 4; ++j) fma2(acc[g][j], hv[j], wv[g]);
        }

        if (wg) {
            ULL* pp = &part[((wg - 1) * 128 + wtid) * 17];
#pragma unroll
            for (int g = 0; g < 4; ++g)
#pragma unroll
                for (int j = 0; j < 4; ++j) pp[g * 4 + j] = acc[g][j];
        }
        __syncthreads();

        if (wg == 0) {
#pragma unroll
            for (int j = 0; j < 4; ++j) {
                int b = b0 + j;
                float gv[4];
#pragma unroll
                for (int g = 0; g < 4; ++g) {
                    ULL s = acc[g][j];
#pragma unroll
                    for (int w = 0; w < 3; ++w)
                        s = f2add(s, part[(w * 128 + wtid) * 17 + g * 4 + j]);
                    gv[g] = f2sum(s) + xg[j * 4 + g];
                }
                float cn = sigf(gv[1]) * creg[j] + sigf(gv[0]) * tanhf(gv[2]);
                float hn = sigf(gv[3]) * tanhf(cn);
                creg[j] = cn;
                hout[(dir * 128 + b) * 256 + uu] = hn;
                ob[((size_t)b * 256 + td) * 512 + dir * 256 + uu] = hn;
            }
            __threadfence();
        }
        __syncthreads();

        if (tid == 0) {
            atomicAdd(&g_bar[grp], 1u);
            unsigned tgt = 16u * (unsigned)(t + 1);
            volatile unsigned* p = &g_bar[grp];
            while (*p < tgt) __nanosleep(32);
            __threadfence();
        }
        __syncthreads();
    }
}

// ---------------- LayerNorm + output projection -------------------------------
__global__ void __launch_bounds__(128) lnfeats(const float* __restrict__ lng,
                                               const float* __restrict__ lnb,
                                               const float* __restrict__ wo,
                                               const float* __restrict__ bo) {
    __shared__ float row[512];
    __shared__ float red[10];
    int i = blockIdx.x, tid = threadIdx.x;
    float4 v = *(const float4*)&g_out1[(size_t)i * 512 + tid * 4];
    float s = v.x + v.y + v.z + v.w;
    float q = v.x * v.x + v.y * v.y + v.z * v.z + v.w * v.w;
#pragma unroll
    for (int o = 16; o; o >>= 1) {
        s += __shfl_xor_sync(0xffffffffu, s, o);
        q += __shfl_xor_sync(0xffffffffu, q, o);
    }
    int wid = tid >> 5, lane = tid & 31;
    if (!lane) { red[wid] = s; red[4 + wid] = q; }
    __syncthreads();
    if (!tid) {
        float S = red[0] + red[1] + red[2] + red[3];
        float Q = red[4] + red[5] + red[6] + red[7];
        float mu = S / 512.f;
        float var = Q / 512.f - mu * mu;
        red[8] = mu;
        red[9] = rsqrtf(var + 1e-5f);
    }
    __syncthreads();
    float mu = red[8], rs = red[9];
    int k = tid * 4;
    row[k + 0] = (v.x - mu) * rs * lng[k + 0] + lnb[k + 0];
    row[k + 1] = (v.y - mu) * rs * lng[k + 1] + lnb[k + 1];
    row[k + 2] = (v.z - mu) * rs * lng[k + 2] + lnb[k + 2];
    row[k + 3] = (v.w - mu) * rs * lng[k + 3] + lnb[k + 3];
    __syncthreads();
    for (int o = wid; o < 22; o += 4) {
        float a = 0.f;
        const float* wr = wo + o * 512;
        for (int k2 = lane; k2 < 512; k2 += 32) a += row[k2] * wr[k2];
#pragma unroll
        for (int off = 16; off; off >>= 1) a += __shfl_xor_sync(0xffffffffu, a, off);
        if (!lane) g_feats[(size_t)i * 22 + o] = a + bo[o];
    }
}

// ---------------- CRF forward + scores (one warp per batch) -------------------
__global__ void crf_k(const float* __restrict__ trans, const int* __restrict__ mask,
                      const int* __restrict__ tags) {
    __shared__ float tr[484];
    __shared__ float alpha[22];
    int b = blockIdx.x, j = threadIdx.x;
    for (int q = j; q < 484; q += 32) tr[q] = trans[q];
    const float* Fb = g_feats + (size_t)b * 256 * 22;
    __syncwarp();
    if (j < 22) alpha[j] = tr[20 * 22 + j] + Fb[j];
    __syncwarp();
    for (int t = 1; t < 256; ++t) {
        float aj = 0.f;
        if (j < 22) {
            float m = -1e30f;
#pragma unroll
            for (int i2 = 0; i2 < 22; ++i2) m = fmaxf(m, alpha[i2] + tr[i2 * 22 + j]);
            float sm = 0.f;
#pragma unroll
            for (int i2 = 0; i2 < 22; ++i2) sm += expf(alpha[i2] + tr[i2 * 22 + j] - m);
            aj = m + logf(sm) + Fb[t * 22 + j];
        }
        int mt = mask[b * 256 + t];
        __syncwarp();
        if (j < 22 && mt) alpha[j] = aj;
        __syncwarp();
    }
    float v = (j < 22) ? alpha[j] + tr[j * 22 + 21] : -1e30f;
    float m = v;
#pragma unroll
    for (int off = 16; off; off >>= 1) m = fmaxf(m, __shfl_xor_sync(0xffffffffu, m, off));
    float e = (j < 22) ? expf(v - m) : 0.f;
#pragma unroll
    for (int off = 16; off; off >>= 1) e += __shfl_xor_sync(0xffffffffu, e, off);
    float logZ = m + logf(e);

    const int* tg = tags + (size_t)b * 256;
    const int* mk = mask + b * 256;
    float emit = 0.f, trs = 0.f;
    int cnt = 0;
    for (int t = j; t < 256; t += 32) {
        if (mk[t]) {
            emit += Fb[t * 22 + tg[t]];
            cnt++;
            if (t >= 1) trs += tr[tg[t - 1] * 22 + tg[t]];
        }
    }
#pragma unroll
    for (int off = 16; off; off >>= 1) {
        emit += __shfl_xor_sync(0xffffffffu, emit, off);
        trs += __shfl_xor_sync(0xffffffffu, trs, off);
        cnt += __shfl_xor_sync(0xffffffffu, cnt, off);
    }
    if (!j) {
        trs += tr[20 * 22 + tg[0]];
        trs += tr[tg[cnt - 1] * 22 + 21];
        g_nll[b] = logZ - emit - trs;
    }
}

__global__ void reduce_nll(float* out) {
    int tid = threadIdx.x;
    float v = g_nll[tid];
#pragma unroll
    for (int off = 16; off; off >>= 1) v += __shfl_xor_sync(0xffffffffu, v, off);
    __shared__ float r[4];
    if (!(tid & 31)) r[tid >> 5] = v;
    __syncthreads();
    if (!tid) out[0] = (r[0] + r[1] + r[2] + r[3]) / 128.f;
}

// ---------------- launcher ----------------
extern "C" void kernel_launch(void* const* d_in, const int* in_sizes, int n_in,
                              void* d_out, int out_size) {
    const float* emb    = (const float*)d_in[0];
    const float* w_ih0  = (const float*)d_in[1];
    const float* w_hh0  = (const float*)d_in[2];
    const float* b_ih0  = (const float*)d_in[3];
    const float* b_hh0  = (const float*)d_in[4];
    const float* w_ih1  = (const float*)d_in[5];
    const float* w_hh1  = (const float*)d_in[6];
    const float* b_ih1  = (const float*)d_in[7];
    const float* b_hh1  = (const float*)d_in[8];
    const float* ln_g   = (const float*)d_in[9];
    const float* ln_b   = (const float*)d_in[10];
    const float* w_out  = (const float*)d_in[11];
    const float* b_out  = (const float*)d_in[12];
    const float* trans  = (const float*)d_in[13];
    const int* words    = (const int*)d_in[14];
    const int* mask     = (const int*)d_in[15];
    const int* tags     = (const int*)d_in[16];
    float* out = (float*)d_out;

    cudaFuncSetAttribute(lstm_persist, cudaFuncAttributeMaxDynamicSharedMemorySize, PERS_SMEM);
    cudaFuncSetAttribute(gemm_tc<256>, cudaFuncAttributeMaxDynamicSharedMemorySize, GT_SMEM);
    cudaFuncSetAttribute(gemm_tc<512>, cudaFuncAttributeMaxDynamicSharedMemorySize, GT_SMEM);

    // layer 0
    embed_bf<<<32768, 256>>>(emb, words);
    conv_w<<<2048, 256>>>(w_ih0);                       // 2048*256 elems
    gemm_tc<256><<<dim3(16, 256), 256, GT_SMEM>>>(b_ih0, b_hh0);
    init_hc<<<512, 256>>>();
    lstm_persist<<<128, 512, PERS_SMEM>>>(w_hh0, 0);
    // layer 1
    conv_a1<<<65536, 256>>>();                          // 32768*512 elems
    conv_w<<<4096, 256>>>(w_ih1);                       // 2048*512 elems
    gemm_tc<512><<<dim3(16, 256), 256, GT_SMEM>>>(b_ih1, b_hh1);
    init_hc<<<512, 256>>>();
    lstm_persist<<<128, 512, PERS_SMEM>>>(w_hh1, 1);
    // head
    lnfeats<<<32768, 128>>>(ln_g, ln_b, w_out, b_out);
    crf_k<<<128, 32>>>(trans, mask, tags);
    reduce_nll<<<1, 128>>>(out);
}

// round 10
// speedup vs baseline: 2.2951x; 1.0448x over previous
#include <cuda_runtime.h>
#include <cuda_bf16.h>
#include <cstdint>

typedef unsigned long long ULL;

// tcgen05 is an arch-SPECIFIC feature: legal in the sm_103a cubin pass,
// illegal in the generic compute_103 PTX pass the harness also emits.
#if !defined(__CUDA_ARCH__) || defined(__CUDA_ARCH_FEAT_SM103_ALL) || \
    defined(__CUDA_ARCH_FEAT_SM100_ALL) || defined(__CUDA_ARCH_SPECIFIC__) || \
    defined(__CUDA_ARCH_FAMILY_SPECIFIC__)
#define TC_OK 1
#else
#define TC_OK 0
#endif

// ---------------- f32x2 helpers (recurrence) ----------------
__device__ __forceinline__ void fma2(ULL& d, ULL a, ULL b) {
    asm("fma.rn.f32x2 %0, %1, %2, %0;" : "+l"(d) : "l"(a), "l"(b));
}
__device__ __forceinline__ ULL f2add(ULL a, ULL b) {
    ULL d;
    asm("add.rn.f32x2 %0, %1, %2;" : "=l"(d) : "l"(a), "l"(b));
    return d;
}
__device__ __forceinline__ float f2sum(ULL v) {
    float x, y;
    asm("mov.b64 {%0,%1}, %2;" : "=f"(x), "=f"(y) : "l"(v));
    return x + y;
}
__device__ __forceinline__ float sigf(float x) { return 1.f / (1.f + expf(-x)); }

// ---------------- tcgen05 helpers (guarded) ----------------
__device__ __forceinline__ uint32_t smem_u32(const void* p) {
    uint32_t a;
    asm("{ .reg .u64 t; cvta.to.shared.u64 t, %1; cvt.u32.u64 %0, t; }" : "=r"(a) : "l"(p));
    return a;
}
#define SW128(o) ((o) ^ (((o) >> 3) & 0x70))
static constexpr uint64_t DESC_BASE_SW128 =
    (uint64_t(2) << 61) | (uint64_t(1) << 46) | (uint64_t(64) << 32) | (uint64_t(1) << 16);
#define MKDESC(a) (DESC_BASE_SW128 | ((uint64_t)((a) >> 4) & 0x3FFF))

#if TC_OK
__device__ __forceinline__ uint32_t elect1() {
    uint32_t p;
    asm volatile("{\n\t.reg .pred p;\n\telect.sync _|p, 0xFFFFFFFF;\n\tselp.b32 %0, 1, 0, p;\n\t}" : "=r"(p));
    return p;
}
#define MBAR_INIT(m, c) asm volatile("mbarrier.init.shared.b64 [%0], %1;" :: "r"(m), "r"(c) : "memory")
#define MBAR_INVAL(m) asm volatile("mbarrier.inval.shared.b64 [%0];" :: "r"(m) : "memory")
#define MBAR_WAIT(m, ph) do { \
    uint32_t _m = (m), _p = (ph), _d; \
    asm volatile("{\n\t.reg .pred p;\n\tmbarrier.try_wait.parity.acquire.cta.shared::cta.b64 p, [%1], %2;\n\tselp.b32 %0,1,0,p;\n\t}" \
        : "=r"(_d) : "r"(_m), "r"(_p) : "memory"); \
    if (!_d) { asm volatile("{\n\t.reg .pred P1;\n\tWL%=:\n\tmbarrier.try_wait.parity.acquire.cta.shared::cta.b64 P1, [%0], %1, 0x989680;\n\t@P1 bra.uni WD%=;\n\tbra.uni WL%=;\n\tWD%=:\n\t}" :: "r"(_m), "r"(_p) : "memory"); } \
} while (0)
#define TC_ALLOC(sa, n)  asm volatile("tcgen05.alloc.cta_group::1.sync.aligned.shared::cta.b32 [%0], %1;" :: "r"(sa), "r"(n) : "memory")
#define TC_RELINQ()      asm volatile("tcgen05.relinquish_alloc_permit.cta_group::1.sync.aligned;")
#define TC_DEALLOC(t, n) asm volatile("tcgen05.dealloc.cta_group::1.sync.aligned.b32 %0, %1;" :: "r"(t), "r"(n))
#define TC_COMMIT(m)     asm volatile("tcgen05.commit.cta_group::1.mbarrier::arrive::one.shared::cluster.b64 [%0];" :: "r"(m) : "memory")
#define TC_WAIT_LD()     asm volatile("tcgen05.wait::ld.sync.aligned;" ::: "memory")
#define TC_FENCE_AFTER() asm volatile("tcgen05.fence::after_thread_sync;" ::: "memory")
#define TC_FENCE_BEFORE() asm volatile("tcgen05.fence::before_thread_sync;" ::: "memory")
#define FENCE_ASYNC()    asm volatile("fence.proxy.async.shared::cta;" ::: "memory")
#define TC_LD_X32(r, a) \
    asm volatile("tcgen05.ld.sync.aligned.32x32b.x32.b32 " \
        "{%0,%1,%2,%3,%4,%5,%6,%7,%8,%9,%10,%11,%12,%13,%14,%15," \
        "%16,%17,%18,%19,%20,%21,%22,%23,%24,%25,%26,%27,%28,%29,%30,%31}, [%32];" \
        : "=r"((r)[0]),"=r"((r)[1]),"=r"((r)[2]),"=r"((r)[3]),"=r"((r)[4]),"=r"((r)[5]),"=r"((r)[6]),"=r"((r)[7]), \
          "=r"((r)[8]),"=r"((r)[9]),"=r"((r)[10]),"=r"((r)[11]),"=r"((r)[12]),"=r"((r)[13]),"=r"((r)[14]),"=r"((r)[15]), \
          "=r"((r)[16]),"=r"((r)[17]),"=r"((r)[18]),"=r"((r)[19]),"=r"((r)[20]),"=r"((r)[21]),"=r"((r)[22]),"=r"((r)[23]), \
          "=r"((r)[24]),"=r"((r)[25]),"=r"((r)[26]),"=r"((r)[27]),"=r"((r)[28]),"=r"((r)[29]),"=r"((r)[30]),"=r"((r)[31]) \
        : "r"(a))
__device__ __forceinline__ void mma_f16_ss(uint32_t d, uint64_t ad, uint64_t bd, uint32_t idesc, uint32_t en) {
    asm volatile(
        "{\n\t.reg .pred p;\n\tsetp.ne.u32 p, %5, 0;\n\t"
        "tcgen05.mma.cta_group::1.kind::f16 [%0], %1, %2, %3, {%4, %4, %4, %4}, p;\n\t}"
        :: "r"(d), "l"(ad), "l"(bd), "r"(idesc), "r"(0u), "r"(en) : "memory");
}
#endif // TC_OK

// M=128, N=128, bf16 x bf16 -> f32
static constexpr uint32_t GEMM_IDESC = (1u << 4) | (1u << 7) | (1u << 10) | (16u << 17) | (8u << 24);

// ---------------- scratch ----------------
__device__ __nv_bfloat16 g_Ah[(size_t)32768 * 512];
__device__ __nv_bfloat16 g_Al[(size_t)32768 * 512];
__device__ __nv_bfloat16 g_Wh[2048 * 512];
__device__ __nv_bfloat16 g_Wl[2048 * 512];
__device__ float g_xg[(size_t)32768 * 2048];
__device__ float g_out0[32768 * 512];
__device__ float g_out1[32768 * 512];
__device__ float g_h[2 * 2 * 128 * 256];
__device__ float g_feats[(size_t)32768 * 22];
__device__ float g_nll[128];
__device__ unsigned g_bar[8];

// ---------------- embedding gather -> bf16 hi/lo (layer0 A, stride 256) ------
__global__ void embed_bf(const float* __restrict__ emb, const int* __restrict__ words) {
    int idx = blockIdx.x * 256 + threadIdx.x;
    int i = idx >> 8, e = idx & 255;
    float x = emb[(size_t)words[i] * 256 + e];
    __nv_bfloat16 h = __float2bfloat16_rn(x);
    g_Ah[idx] = h;
    g_Al[idx] = __float2bfloat16_rn(x - __bfloat162float(h));
}

// ---------------- fp32 -> bf16 hi/lo converters ----------------
__global__ void conv_a1(void) {   // g_out0 [32768][512] -> g_Ah/g_Al stride 512
    size_t idx = (size_t)blockIdx.x * 256 + threadIdx.x;
    float x = g_out0[idx];
    __nv_bfloat16 h = __float2bfloat16_rn(x);
    g_Ah[idx] = h;
    g_Al[idx] = __float2bfloat16_rn(x - __bfloat162float(h));
}
__global__ void conv_w(const float* __restrict__ W) {  // [2048][K] flat
    size_t idx = (size_t)blockIdx.x * 256 + threadIdx.x;
    float x = W[idx];
    __nv_bfloat16 h = __float2bfloat16_rn(x);
    g_Wh[idx] = h;
    g_Wl[idx] = __float2bfloat16_rn(x - __bfloat162float(h));
}

// ---------------- tcgen05 input-projection GEMM (round-9, passing) ------------
#define GT_SMEM (1024 + 4 * 16384)
template <int K>
__global__ void __launch_bounds__(256, 2)
gemm_tc(const float* __restrict__ bi, const float* __restrict__ bh) {
#if TC_OK
    extern __shared__ char smx[];
    uint32_t sb = smem_u32(smx);
    const int SM_TM = 0, SM_MB = 8;
    const int SM_AH = 1024, SM_AL = SM_AH + 16384, SM_WH = SM_AL + 16384, SM_WL = SM_WH + 16384;

    int tid = threadIdx.x, wid = tid >> 5, lid = tid & 31;
    int nt = blockIdx.x, mt = blockIdx.y;

    if (wid == 0) {
        TC_ALLOC(sb + SM_TM, 128);
        TC_RELINQ();
    }
    if (tid == 0) MBAR_INIT(sb + SM_MB, 1);
    __syncthreads();
    uint32_t tmem;
    asm volatile("ld.shared.b32 %0, [%1];" : "=r"(tmem) : "r"(sb + SM_TM));

    const int NC = K / 64;
    for (int ci = 0; ci < NC; ++ci) {
#pragma unroll
        for (int i = 0; i < 4; ++i) {
            int idx = i * 256 + tid;
            int r = idx >> 3, c8 = idx & 7;
            uint32_t so = SW128((uint32_t)(r * 128 + c8 * 16));
            size_t ga = (size_t)(mt * 128 + r) * K + ci * 64 + c8 * 8;
            *(uint4*)(smx + SM_AH + so) = *(const uint4*)(g_Ah + ga);
            *(uint4*)(smx + SM_AL + so) = *(const uint4*)(g_Al + ga);
            size_t gw = (size_t)(nt * 128 + r) * K + ci * 64 + c8 * 8;
            *(uint4*)(smx + SM_WH + so) = *(const uint4*)(g_Wh + gw);
            *(uint4*)(smx + SM_WL + so) = *(const uint4*)(g_Wl + gw);
        }
        FENCE_ASYNC();
        __syncthreads();

        if (wid == 0 && elect1()) {
            uint64_t dAh = MKDESC(sb + SM_AH), dAl = MKDESC(sb + SM_AL);
            uint64_t dWh = MKDESC(sb + SM_WH), dWl = MKDESC(sb + SM_WL);
#pragma unroll
            for (int k = 0; k < 4; ++k) {
                uint64_t o = k * 2;
                mma_f16_ss(tmem, dAh + o, dWh + o, GEMM_IDESC, !(ci == 0 && k == 0));
                mma_f16_ss(tmem, dAh + o, dWl + o, GEMM_IDESC, 1u);
                mma_f16_ss(tmem, dAl + o, dWh + o, GEMM_IDESC, 1u);
            }
            TC_COMMIT(sb + SM_MB);
        }
        MBAR_WAIT(sb + SM_MB, (uint32_t)(ci & 1));
        __syncthreads();
    }

    TC_FENCE_AFTER();
    if (wid < 4) {
        int m = mt * 128 + wid * 32 + lid;
#pragma unroll
        for (int nb = 0; nb < 4; ++nb) {
            uint32_t dr[32];
            TC_LD_X32(dr, tmem + nb * 32);
            TC_WAIT_LD();
            int n0 = nt * 128 + nb * 32;
#pragma unroll
            for (int c8 = 0; c8 < 8; ++c8) {
                float4 o;
                int n = n0 + c8 * 4;
                o.x = __uint_as_float(dr[c8 * 4 + 0]) + bi[n + 0] + bh[n + 0];
                o.y = __uint_as_float(dr[c8 * 4 + 1]) + bi[n + 1] + bh[n + 1];
                o.z = __uint_as_float(dr[c8 * 4 + 2]) + bi[n + 2] + bh[n + 2];
                o.w = __uint_as_float(dr[c8 * 4 + 3]) + bi[n + 3] + bh[n + 3];
                *(float4*)&g_xg[(size_t)m * 2048 + n] = o;
            }
        }
    }
    TC_FENCE_BEFORE();
    __syncthreads();
    if (tid == 0) MBAR_INVAL(sb + SM_MB);
    if (wid == 0) TC_DEALLOC(tmem, 128);
#else
    // Correct SIMT fallback for the generic compute_103 PTX pass (never runs).
    int tid = threadIdx.x;
    int nt = blockIdx.x, mt = blockIdx.y;
    for (int q = tid; q < 128 * 128; q += 256) {
        int mi = q >> 7, ni = q & 127;
        int m = mt * 128 + mi, n = nt * 128 + ni;
        float s = 0.f;
        for (int k = 0; k < K; ++k) {
            float a = __bfloat162float(g_Ah[(size_t)m * K + k]) + __bfloat162float(g_Al[(size_t)m * K + k]);
            float w = __bfloat162float(g_Wh[(size_t)n * K + k]) + __bfloat162float(g_Wl[(size_t)n * K + k]);
            s += a * w;
        }
        g_xg[(size_t)m * 2048 + n] = s + bi[n] + bh[n];
    }
#endif
}

// ---------------- zero h pings + group barriers ----------------
__global__ void init_hc() {
    int i = blockIdx.x * 256 + threadIdx.x;
    g_h[i] = 0.f;
    if (i < 8) g_bar[i] = 0u;
}

// ---------------- persistent BiLSTM layer v5 ----------------------------------
// 128 blocks: dir(2) x bch(4 of 32 batches) x uch(16 of 16 units); all resident.
// 512 threads: wg = tid>>7 splits K 4 ways; wtid = tid&127: u = wtid&15, bg = wtid>>4.
// v5 changes vs proven v2: (1) ALL 4 wgs store partials; distributed epilogue =
// exactly one (batch,unit) cell per thread; (2) ob store + next-step xg prefetch
// moved AFTER the barrier arrive (hidden in the wait); (3) xg is 4 regs/thread.
#define PERS_SMEM ((64 * 258 + 32 * 258) * 4 + 4 * 128 * 17 * 8)
__global__ void __launch_bounds__(512) lstm_persist(const float* __restrict__ whh, int layer) {
    extern __shared__ float sm[];
    float* ws = sm;                       // [64][258] rows: g*16+u
    float* hs = sm + 64 * 258;            // [32][258]
    ULL* part = (ULL*)(sm + 96 * 258);    // [4][128][17]

    int bx = blockIdx.x;
    int dir = bx & 1, bch = (bx >> 1) & 3, uch = bx >> 3;
    int grp = bx & 7;
    int tid = threadIdx.x;
    int wg = tid >> 7, wtid = tid & 127;
    int u = wtid & 15, bg = wtid >> 4;

    // epilogue cell: one (batch, unit) per thread
    int u_l = tid & 15, b_l = tid >> 4;            // u_l 0..15, b_l 0..31
    int uu_e = uch * 16 + u_l;
    int b_e = bch * 32 + b_l;
    int src = (b_l >> 2) * 16 + u_l;               // producing wtid
    int jj = b_l & 3;                              // j within producer

    const float* wb = whh + (size_t)dir * 1024 * 256;
#pragma unroll 4
    for (int r = 0; r < 16; ++r) {
        int q = r * 512 + tid;
        int wrow = q >> 7, cc = q & 127;
        int gt = wrow >> 4, uw = wrow & 15;
        *(float2*)&ws[wrow * 258 + cc * 2] =
            *(const float2*)&wb[(size_t)(gt * 256 + uch * 16 + uw) * 256 + cc * 2];
    }

    float creg = 0.f;
    float* ob = layer ? g_out1 : g_out0;
    const int kbase = wg * 64;

    // prefetch xg for t = 0
    float xg[4];
    {
        int td0 = dir ? 255 : 0;
        size_t xb = ((size_t)b_e * 256 + td0) * 2048 + dir * 1024 + uu_e;
        xg[0] = __ldcg(&g_xg[xb]);
        xg[1] = __ldcg(&g_xg[xb + 256]);
        xg[2] = __ldcg(&g_xg[xb + 512]);
        xg[3] = __ldcg(&g_xg[xb + 768]);
    }

    for (int t = 0; t < 256; ++t) {
        int td = dir ? 255 - t : t;
        const float* hin = g_h + (t & 1) * (2 * 128 * 256);
        float* hout = g_h + ((t & 1) ^ 1) * (2 * 128 * 256);

        // stage h_{t-1}: 4096 float2, 8 per thread (.cg bypasses stale L1)
        const float* hb = hin + (dir * 128 + bch * 32) * 256;
#pragma unroll
        for (int r = 0; r < 8; ++r) {
            int q = r * 512 + tid;
            int row = q >> 7, cc = q & 127;
            *(float2*)&hs[row * 258 + cc * 2] = __ldcg((const float2*)&hb[row * 256 + cc * 2]);
        }
        __syncthreads();

        ULL acc[4][4] = {};
#pragma unroll 8
        for (int kp = 0; kp < 32; ++kp) {
            ULL hv[4], wv[4];
#pragma unroll
            for (int j = 0; j < 4; ++j)
                hv[j] = *(const ULL*)&hs[(bg * 4 + j) * 258 + kbase + kp * 2];
#pragma unroll
            for (int g = 0; g < 4; ++g)
                wv[g] = *(const ULL*)&ws[(g * 16 + u) * 258 + kbase + kp * 2];
#pragma unroll
            for (int g = 0; g < 4; ++g)
#pragma unroll
                for (int j = 0; j < 4; ++j) fma2(acc[g][j], hv[j], wv[g]);
        }

        // all wgs publish partials
        {
            ULL* pp = &part[(wg * 128 + wtid) * 17];
#pragma unroll
            for (int g = 0; g < 4; ++g)
#pragma unroll
                for (int j = 0; j < 4; ++j) pp[g * 4 + j] = acc[g][j];
        }
        __syncthreads();

        // distributed epilogue: one cell per thread
        float hn;
        {
            float gv[4];
#pragma unroll
            for (int g = 0; g < 4; ++g) {
                ULL s = part[src * 17 + g * 4 + jj];
#pragma unroll
                for (int w = 1; w < 4; ++w)
                    s = f2add(s, part[(w * 128 + src) * 17 + g * 4 + jj]);
                gv[g] = f2sum(s) + xg[g];
            }
            float cn = sigf(gv[1]) * creg + sigf(gv[0]) * tanhf(gv[2]);
            hn = sigf(gv[3]) * tanhf(cn);
            creg = cn;
            hout[(dir * 128 + b_e) * 256 + uu_e] = hn;
        }
        __threadfence();
        __syncthreads();

        // arrive, then hide ob store + next xg prefetch inside the wait
        if (tid == 0) atomicAdd(&g_bar[grp], 1u);
        ob[((size_t)b_e * 256 + td) * 512 + dir * 256 + uu_e] = hn;
        if (t + 1 < 256) {
            int td2 = dir ? 255 - (t + 1) : t + 1;
            size_t xb = ((size_t)b_e * 256 + td2) * 2048 + dir * 1024 + uu_e;
            xg[0] = __ldcg(&g_xg[xb]);
            xg[1] = __ldcg(&g_xg[xb + 256]);
            xg[2] = __ldcg(&g_xg[xb + 512]);
            xg[3] = __ldcg(&g_xg[xb + 768]);
        }
        if (tid == 0) {
            unsigned tgt = 16u * (unsigned)(t + 1);
            volatile unsigned* p = &g_bar[grp];
            while (*p < tgt) __nanosleep(32);
            __threadfence();
        }
        __syncthreads();
    }
}

// ---------------- LayerNorm + output projection -------------------------------
__global__ void __launch_bounds__(128) lnfeats(const float* __restrict__ lng,
                                               const float* __restrict__ lnb,
                                               const float* __restrict__ wo,
                                               const float* __restrict__ bo) {
    __shared__ float row[512];
    __shared__ float red[10];
    int i = blockIdx.x, tid = threadIdx.x;
    float4 v = *(const float4*)&g_out1[(size_t)i * 512 + tid * 4];
    float s = v.x + v.y + v.z + v.w;
    float q = v.x * v.x + v.y * v.y + v.z * v.z + v.w * v.w;
#pragma unroll
    for (int o = 16; o; o >>= 1) {
        s += __shfl_xor_sync(0xffffffffu, s, o);
        q += __shfl_xor_sync(0xffffffffu, q, o);
    }
    int wid = tid >> 5, lane = tid & 31;
    if (!lane) { red[wid] = s; red[4 + wid] = q; }
    __syncthreads();
    if (!tid) {
        float S = red[0] + red[1] + red[2] + red[3];
        float Q = red[4] + red[5] + red[6] + red[7];
        float mu = S / 512.f;
        float var = Q / 512.f - mu * mu;
        red[8] = mu;
        red[9] = rsqrtf(var + 1e-5f);
    }
    __syncthreads();
    float mu = red[8], rs = red[9];
    int k = tid * 4;
    row[k + 0] = (v.x - mu) * rs * lng[k + 0] + lnb[k + 0];
    row[k + 1] = (v.y - mu) * rs * lng[k + 1] + lnb[k + 1];
    row[k + 2] = (v.z - mu) * rs * lng[k + 2] + lnb[k + 2];
    row[k + 3] = (v.w - mu) * rs * lng[k + 3] + lnb[k + 3];
    __syncthreads();
    for (int o = wid; o < 22; o += 4) {
        float a = 0.f;
        const float* wr = wo + o * 512;
        for (int k2 = lane; k2 < 512; k2 += 32) a += row[k2] * wr[k2];
#pragma unroll
        for (int off = 16; off; off >>= 1) a += __shfl_xor_sync(0xffffffffu, a, off);
        if (!lane) g_feats[(size_t)i * 22 + o] = a + bo[o];
    }
}

// ---------------- CRF forward + scores (one warp per batch) -------------------
__global__ void crf_k(const float* __restrict__ trans, const int* __restrict__ mask,
                      const int* __restrict__ tags) {
    __shared__ float tr[484];
    __shared__ float alpha[22];
    int b = blockIdx.x, j = threadIdx.x;
    for (int q = j; q < 484; q += 32) tr[q] = trans[q];
    const float* Fb = g_feats + (size_t)b * 256 * 22;
    __syncwarp();
    if (j < 22) alpha[j] = tr[20 * 22 + j] + Fb[j];
    __syncwarp();
    for (int t = 1; t < 256; ++t) {
        float aj = 0.f;
        if (j < 22) {
            float m = -1e30f;
#pragma unroll
            for (int i2 = 0; i2 < 22; ++i2) m = fmaxf(m, alpha[i2] + tr[i2 * 22 + j]);
            float sm = 0.f;
#pragma unroll
            for (int i2 = 0; i2 < 22; ++i2) sm += expf(alpha[i2] + tr[i2 * 22 + j] - m);
            aj = m + logf(sm) + Fb[t * 22 + j];
        }
        int mt = mask[b * 256 + t];
        __syncwarp();
        if (j < 22 && mt) alpha[j] = aj;
        __syncwarp();
    }
    float v = (j < 22) ? alpha[j] + tr[j * 22 + 21] : -1e30f;
    float m = v;
#pragma unroll
    for (int off = 16; off; off >>= 1) m = fmaxf(m, __shfl_xor_sync(0xffffffffu, m, off));
    float e = (j < 22) ? expf(v - m) : 0.f;
#pragma unroll
    for (int off = 16; off; off >>= 1) e += __shfl_xor_sync(0xffffffffu, e, off);
    float logZ = m + logf(e);

    const int* tg = tags + (size_t)b * 256;
    const int* mk = mask + b * 256;
    float emit = 0.f, trs = 0.f;
    int cnt = 0;
    for (int t = j; t < 256; t += 32) {
        if (mk[t]) {
            emit += Fb[t * 22 + tg[t]];
            cnt++;
            if (t >= 1) trs += tr[tg[t - 1] * 22 + tg[t]];
        }
    }
#pragma unroll
    for (int off = 16; off; off >>= 1) {
        emit += __shfl_xor_sync(0xffffffffu, emit, off);
        trs += __shfl_xor_sync(0xffffffffu, trs, off);
        cnt += __shfl_xor_sync(0xffffffffu, cnt, off);
    }
    if (!j) {
        trs += tr[20 * 22 + tg[0]];
        trs += tr[tg[cnt - 1] * 22 + 21];
        g_nll[b] = logZ - emit - trs;
    }
}

__global__ void reduce_nll(float* out) {
    int tid = threadIdx.x;
    float v = g_nll[tid];
#pragma unroll
    for (int off = 16; off; off >>= 1) v += __shfl_xor_sync(0xffffffffu, v, off);
    __shared__ float r[4];
    if (!(tid & 31)) r[tid >> 5] = v;
    __syncthreads();
    if (!tid) out[0] = (r[0] + r[1] + r[2] + r[3]) / 128.f;
}

// ---------------- launcher ----------------
extern "C" void kernel_launch(void* const* d_in, const int* in_sizes, int n_in,
                              void* d_out, int out_size) {
    const float* emb    = (const float*)d_in[0];
    const float* w_ih0  = (const float*)d_in[1];
    const float* w_hh0  = (const float*)d_in[2];
    const float* b_ih0  = (const float*)d_in[3];
    const float* b_hh0  = (const float*)d_in[4];
    const float* w_ih1  = (const float*)d_in[5];
    const float* w_hh1  = (const float*)d_in[6];
    const float* b_ih1  = (const float*)d_in[7];
    const float* b_hh1  = (const float*)d_in[8];
    const float* ln_g   = (const float*)d_in[9];
    const float* ln_b   = (const float*)d_in[10];
    const float* w_out  = (const float*)d_in[11];
    const float* b_out  = (const float*)d_in[12];
    const float* trans  = (const float*)d_in[13];
    const int* words    = (const int*)d_in[14];
    const int* mask     = (const int*)d_in[15];
    const int* tags     = (const int*)d_in[16];
    float* out = (float*)d_out;

    cudaFuncSetAttribute(lstm_persist, cudaFuncAttributeMaxDynamicSharedMemorySize, PERS_SMEM);
    cudaFuncSetAttribute(gemm_tc<256>, cudaFuncAttributeMaxDynamicSharedMemorySize, GT_SMEM);
    cudaFuncSetAttribute(gemm_tc<512>, cudaFuncAttributeMaxDynamicSharedMemorySize, GT_SMEM);

    // layer 0
    embed_bf<<<32768, 256>>>(emb, words);
    conv_w<<<2048, 256>>>(w_ih0);
    gemm_tc<256><<<dim3(16, 256), 256, GT_SMEM>>>(b_ih0, b_hh0);
    init_hc<<<512, 256>>>();
    lstm_persist<<<128, 512, PERS_SMEM>>>(w_hh0, 0);
    // layer 1
    conv_a1<<<65536, 256>>>();
    conv_w<<<4096, 256>>>(w_ih1);
    gemm_tc<512><<<dim3(16, 256), 256, GT_SMEM>>>(b_ih1, b_hh1);
    init_hc<<<512, 256>>>();
    lstm_persist<<<128, 512, PERS_SMEM>>>(w_hh1, 1);
    // head
    lnfeats<<<32768, 128>>>(ln_g, ln_b, w_out, b_out);
    crf_k<<<128, 32>>>(trans, mask, tags);
    reduce_nll<<<1, 128>>>(out);
}

// round 11
// speedup vs baseline: 2.5781x; 1.1233x over previous
#include <cuda_runtime.h>
#include <cuda_bf16.h>
#include <cstdint>

typedef unsigned long long ULL;

// tcgen05 is an arch-SPECIFIC feature: legal in the sm_103a cubin pass,
// illegal in the generic compute_103 PTX pass the harness also emits.
#if !defined(__CUDA_ARCH__) || defined(__CUDA_ARCH_FEAT_SM103_ALL) || \
    defined(__CUDA_ARCH_FEAT_SM100_ALL) || defined(__CUDA_ARCH_SPECIFIC__) || \
    defined(__CUDA_ARCH_FAMILY_SPECIFIC__)
#define TC_OK 1
#else
#define TC_OK 0
#endif

// ---------------- f32x2 helpers (recurrence) ----------------
__device__ __forceinline__ void fma2(ULL& d, ULL a, ULL b) {
    asm("fma.rn.f32x2 %0, %1, %2, %0;" : "+l"(d) : "l"(a), "l"(b));
}
__device__ __forceinline__ ULL f2add(ULL a, ULL b) {
    ULL d;
    asm("add.rn.f32x2 %0, %1, %2;" : "=l"(d) : "l"(a), "l"(b));
    return d;
}
__device__ __forceinline__ float f2sum(ULL v) {
    float x, y;
    asm("mov.b64 {%0,%1}, %2;" : "=f"(x), "=f"(y) : "l"(v));
    return x + y;
}
__device__ __forceinline__ float sigf(float x) { return 1.f / (1.f + expf(-x)); }

// ---------------- tcgen05 helpers (guarded) ----------------
__device__ __forceinline__ uint32_t smem_u32(const void* p) {
    uint32_t a;
    asm("{ .reg .u64 t; cvta.to.shared.u64 t, %1; cvt.u32.u64 %0, t; }" : "=r"(a) : "l"(p));
    return a;
}
#define SW128(o) ((o) ^ (((o) >> 3) & 0x70))
static constexpr uint64_t DESC_BASE_SW128 =
    (uint64_t(2) << 61) | (uint64_t(1) << 46) | (uint64_t(64) << 32) | (uint64_t(1) << 16);
#define MKDESC(a) (DESC_BASE_SW128 | ((uint64_t)((a) >> 4) & 0x3FFF))

#if TC_OK
__device__ __forceinline__ uint32_t elect1() {
    uint32_t p;
    asm volatile("{\n\t.reg .pred p;\n\telect.sync _|p, 0xFFFFFFFF;\n\tselp.b32 %0, 1, 0, p;\n\t}" : "=r"(p));
    return p;
}
#define MBAR_INIT(m, c) asm volatile("mbarrier.init.shared.b64 [%0], %1;" :: "r"(m), "r"(c) : "memory")
#define MBAR_INVAL(m) asm volatile("mbarrier.inval.shared.b64 [%0];" :: "r"(m) : "memory")
#define MBAR_WAIT(m, ph) do { \
    uint32_t _m = (m), _p = (ph), _d; \
    asm volatile("{\n\t.reg .pred p;\n\tmbarrier.try_wait.parity.acquire.cta.shared::cta.b64 p, [%1], %2;\n\tselp.b32 %0,1,0,p;\n\t}" \
        : "=r"(_d) : "r"(_m), "r"(_p) : "memory"); \
    if (!_d) { asm volatile("{\n\t.reg .pred P1;\n\tWL%=:\n\tmbarrier.try_wait.parity.acquire.cta.shared::cta.b64 P1, [%0], %1, 0x989680;\n\t@P1 bra.uni WD%=;\n\tbra.uni WL%=;\n\tWD%=:\n\t}" :: "r"(_m), "r"(_p) : "memory"); } \
} while (0)
#define TC_ALLOC(sa, n)  asm volatile("tcgen05.alloc.cta_group::1.sync.aligned.shared::cta.b32 [%0], %1;" :: "r"(sa), "r"(n) : "memory")
#define TC_RELINQ()      asm volatile("tcgen05.relinquish_alloc_permit.cta_group::1.sync.aligned;")
#define TC_DEALLOC(t, n) asm volatile("tcgen05.dealloc.cta_group::1.sync.aligned.b32 %0, %1;" :: "r"(t), "r"(n))
#define TC_COMMIT(m)     asm volatile("tcgen05.commit.cta_group::1.mbarrier::arrive::one.shared::cluster.b64 [%0];" :: "r"(m) : "memory")
#define TC_WAIT_LD()     asm volatile("tcgen05.wait::ld.sync.aligned;" ::: "memory")
#define TC_FENCE_AFTER() asm volatile("tcgen05.fence::after_thread_sync;" ::: "memory")
#define TC_FENCE_BEFORE() asm volatile("tcgen05.fence::before_thread_sync;" ::: "memory")
#define FENCE_ASYNC()    asm volatile("fence.proxy.async.shared::cta;" ::: "memory")
#define TC_LD_X32(r, a) \
    asm volatile("tcgen05.ld.sync.aligned.32x32b.x32.b32 " \
        "{%0,%1,%2,%3,%4,%5,%6,%7,%8,%9,%10,%11,%12,%13,%14,%15," \
        "%16,%17,%18,%19,%20,%21,%22,%23,%24,%25,%26,%27,%28,%29,%30,%31}, [%32];" \
        : "=r"((r)[0]),"=r"((r)[1]),"=r"((r)[2]),"=r"((r)[3]),"=r"((r)[4]),"=r"((r)[5]),"=r"((r)[6]),"=r"((r)[7]), \
          "=r"((r)[8]),"=r"((r)[9]),"=r"((r)[10]),"=r"((r)[11]),"=r"((r)[12]),"=r"((r)[13]),"=r"((r)[14]),"=r"((r)[15]), \
          "=r"((r)[16]),"=r"((r)[17]),"=r"((r)[18]),"=r"((r)[19]),"=r"((r)[20]),"=r"((r)[21]),"=r"((r)[22]),"=r"((r)[23]), \
          "=r"((r)[24]),"=r"((r)[25]),"=r"((r)[26]),"=r"((r)[27]),"=r"((r)[28]),"=r"((r)[29]),"=r"((r)[30]),"=r"((r)[31]) \
        : "r"(a))
__device__ __forceinline__ void mma_f16_ss(uint32_t d, uint64_t ad, uint64_t bd, uint32_t idesc, uint32_t en) {
    asm volatile(
        "{\n\t.reg .pred p;\n\tsetp.ne.u32 p, %5, 0;\n\t"
        "tcgen05.mma.cta_group::1.kind::f16 [%0], %1, %2, %3, {%4, %4, %4, %4}, p;\n\t}"
        :: "r"(d), "l"(ad), "l"(bd), "r"(idesc), "r"(0u), "r"(en) : "memory");
}
#endif // TC_OK

// M=128, N=128, bf16 x bf16 -> f32
static constexpr uint32_t GEMM_IDESC = (1u << 4) | (1u << 7) | (1u << 10) | (16u << 17) | (8u << 24);

// ---------------- scratch ----------------
__device__ __nv_bfloat16 g_Ah[(size_t)32768 * 512];
__device__ __nv_bfloat16 g_Al[(size_t)32768 * 512];
__device__ __nv_bfloat16 g_Wh[2048 * 512];
__device__ __nv_bfloat16 g_Wl[2048 * 512];
__device__ float g_xg[(size_t)32768 * 2048];
__device__ float g_out0[32768 * 512];
__device__ float g_out1[32768 * 512];
__device__ float g_h[2 * 2 * 128 * 256];
__device__ float g_feats[(size_t)32768 * 22];
__device__ float g_nll[128];
__device__ unsigned g_bar[16];

// ---------------- release/acquire barrier primitives ----------------
__device__ __forceinline__ void bar_arrive_rel(unsigned* p) {
    asm volatile("red.release.gpu.global.add.u32 [%0], %1;" :: "l"(p), "r"(1u) : "memory");
}
__device__ __forceinline__ unsigned bar_ld_acq(unsigned* p) {
    unsigned v;
    asm volatile("ld.acquire.gpu.global.u32 %0, [%1];" : "=r"(v) : "l"(p) : "memory");
    return v;
}

// ---------------- embedding gather -> bf16 hi/lo (layer0 A, stride 256) ------
__global__ void embed_bf(const float* __restrict__ emb, const int* __restrict__ words) {
    int idx = blockIdx.x * 256 + threadIdx.x;
    int i = idx >> 8, e = idx & 255;
    float x = emb[(size_t)words[i] * 256 + e];
    __nv_bfloat16 h = __float2bfloat16_rn(x);
    g_Ah[idx] = h;
    g_Al[idx] = __float2bfloat16_rn(x - __bfloat162float(h));
}

// ---------------- fp32 -> bf16 hi/lo converters ----------------
__global__ void conv_a1(void) {
    size_t idx = (size_t)blockIdx.x * 256 + threadIdx.x;
    float x = g_out0[idx];
    __nv_bfloat16 h = __float2bfloat16_rn(x);
    g_Ah[idx] = h;
    g_Al[idx] = __float2bfloat16_rn(x - __bfloat162float(h));
}
__global__ void conv_w(const float* __restrict__ W) {
    size_t idx = (size_t)blockIdx.x * 256 + threadIdx.x;
    float x = W[idx];
    __nv_bfloat16 h = __float2bfloat16_rn(x);
    g_Wh[idx] = h;
    g_Wl[idx] = __float2bfloat16_rn(x - __bfloat162float(h));
}

// ---------------- tcgen05 input-projection GEMM (round-9, passing) ------------
#define GT_SMEM (1024 + 4 * 16384)
template <int K>
__global__ void __launch_bounds__(256, 2)
gemm_tc(const float* __restrict__ bi, const float* __restrict__ bh) {
#if TC_OK
    extern __shared__ char smx[];
    uint32_t sb = smem_u32(smx);
    const int SM_TM = 0, SM_MB = 8;
    const int SM_AH = 1024, SM_AL = SM_AH + 16384, SM_WH = SM_AL + 16384, SM_WL = SM_WH + 16384;

    int tid = threadIdx.x, wid = tid >> 5, lid = tid & 31;
    int nt = blockIdx.x, mt = blockIdx.y;

    if (wid == 0) {
        TC_ALLOC(sb + SM_TM, 128);
        TC_RELINQ();
    }
    if (tid == 0) MBAR_INIT(sb + SM_MB, 1);
    __syncthreads();
    uint32_t tmem;
    asm volatile("ld.shared.b32 %0, [%1];" : "=r"(tmem) : "r"(sb + SM_TM));

    const int NC = K / 64;
    for (int ci = 0; ci < NC; ++ci) {
#pragma unroll
        for (int i = 0; i < 4; ++i) {
            int idx = i * 256 + tid;
            int r = idx >> 3, c8 = idx & 7;
            uint32_t so = SW128((uint32_t)(r * 128 + c8 * 16));
            size_t ga = (size_t)(mt * 128 + r) * K + ci * 64 + c8 * 8;
            *(uint4*)(smx + SM_AH + so) = *(const uint4*)(g_Ah + ga);
            *(uint4*)(smx + SM_AL + so) = *(const uint4*)(g_Al + ga);
            size_t gw = (size_t)(nt * 128 + r) * K + ci * 64 + c8 * 8;
            *(uint4*)(smx + SM_WH + so) = *(const uint4*)(g_Wh + gw);
            *(uint4*)(smx + SM_WL + so) = *(const uint4*)(g_Wl + gw);
        }
        FENCE_ASYNC();
        __syncthreads();

        if (wid == 0 && elect1()) {
            uint64_t dAh = MKDESC(sb + SM_AH), dAl = MKDESC(sb + SM_AL);
            uint64_t dWh = MKDESC(sb + SM_WH), dWl = MKDESC(sb + SM_WL);
#pragma unroll
            for (int k = 0; k < 4; ++k) {
                uint64_t o = k * 2;
                mma_f16_ss(tmem, dAh + o, dWh + o, GEMM_IDESC, !(ci == 0 && k == 0));
                mma_f16_ss(tmem, dAh + o, dWl + o, GEMM_IDESC, 1u);
                mma_f16_ss(tmem, dAl + o, dWh + o, GEMM_IDESC, 1u);
            }
            TC_COMMIT(sb + SM_MB);
        }
        MBAR_WAIT(sb + SM_MB, (uint32_t)(ci & 1));
        __syncthreads();
    }

    TC_FENCE_AFTER();
    if (wid < 4) {
        int m = mt * 128 + wid * 32 + lid;
#pragma unroll
        for (int nb = 0; nb < 4; ++nb) {
            uint32_t dr[32];
            TC_LD_X32(dr, tmem + nb * 32);
            TC_WAIT_LD();
            int n0 = nt * 128 + nb * 32;
#pragma unroll
            for (int c8 = 0; c8 < 8; ++c8) {
                float4 o;
                int n = n0 + c8 * 4;
                o.x = __uint_as_float(dr[c8 * 4 + 0]) + bi[n + 0] + bh[n + 0];
                o.y = __uint_as_float(dr[c8 * 4 + 1]) + bi[n + 1] + bh[n + 1];
                o.z = __uint_as_float(dr[c8 * 4 + 2]) + bi[n + 2] + bh[n + 2];
                o.w = __uint_as_float(dr[c8 * 4 + 3]) + bi[n + 3] + bh[n + 3];
                *(float4*)&g_xg[(size_t)m * 2048 + n] = o;
            }
        }
    }
    TC_FENCE_BEFORE();
    __syncthreads();
    if (tid == 0) MBAR_INVAL(sb + SM_MB);
    if (wid == 0) TC_DEALLOC(tmem, 128);
#else
    // Correct SIMT fallback for the generic compute_103 PTX pass (never runs).
    int tid = threadIdx.x;
    int nt = blockIdx.x, mt = blockIdx.y;
    for (int q = tid; q < 128 * 128; q += 256) {
        int mi = q >> 7, ni = q & 127;
        int m = mt * 128 + mi, n = nt * 128 + ni;
        float s = 0.f;
        for (int k = 0; k < K; ++k) {
            float a = __bfloat162float(g_Ah[(size_t)m * K + k]) + __bfloat162float(g_Al[(size_t)m * K + k]);
            float w = __bfloat162float(g_Wh[(size_t)n * K + k]) + __bfloat162float(g_Wl[(size_t)n * K + k]);
            s += a * w;
        }
        g_xg[(size_t)m * 2048 + n] = s + bi[n] + bh[n];
    }
#endif
}

// ---------------- zero h pings + group barriers ----------------
__global__ void init_hc() {
    int i = blockIdx.x * 256 + threadIdx.x;
    g_h[i] = 0.f;
    if (i < 16) g_bar[i] = 0u;
}

// ---------------- persistent BiLSTM layer v6 ----------------------------------
// 128 blocks: bx bit0 = dir, bits1-3 = bch (8 groups of 16 batches),
// bits4-6 = uch (8 chunks of 32 units). Barrier group = (dir,bch) -> 8 blocks.
// 512 threads: wg = tid>>7 splits K 4 ways; wtid = tid&127: u = wtid&31 (unit),
// bg = wtid>>5 (4 groups x 4 batches). W_hh slice = 128 rows x 256 k in smem.
// Sync: syncthreads -> tid0 red.release.gpu -> ob/xg shadow work ->
// tid0 ld.acquire.gpu poll -> syncthreads (no threadfence, no nanosleep).
#define PERS_SMEM ((128 * 258 + 16 * 258) * 4 + 4 * 128 * 17 * 8)
__global__ void __launch_bounds__(512) lstm_persist(const float* __restrict__ whh, int layer) {
    extern __shared__ float sm[];
    float* ws = sm;                        // [128][258] rows: g*32 + u
    float* hs = sm + 128 * 258;            // [16][258]
    ULL* part = (ULL*)(sm + 144 * 258);    // [4][128][17]

    int bx = blockIdx.x;
    int dir = bx & 1, bch = (bx >> 1) & 7, uch = bx >> 4;
    int grp = bx & 15;
    int tid = threadIdx.x;
    int wg = tid >> 7, wtid = tid & 127;
    int u = wtid & 31, bg = wtid >> 5;

    // epilogue cell: one (batch, unit) per thread
    int u_l = tid & 31, b_l = tid >> 5;            // u_l 0..31, b_l 0..15
    int uu_e = uch * 32 + u_l;
    int b_e = bch * 16 + b_l;
    int src = (b_l >> 2) * 32 + u_l;               // producing wtid
    int jj = b_l & 3;                              // j within producer

    // stage W_hh slice once: 128 rows (4 gates x 32 units) x 256 k = 16384 float2
    const float* wb = whh + (size_t)dir * 1024 * 256;
#pragma unroll 4
    for (int r = 0; r < 32; ++r) {
        int q = r * 512 + tid;
        int wrow = q >> 7, cc = q & 127;
        int gt = wrow >> 5, uw = wrow & 31;
        *(float2*)&ws[wrow * 258 + cc * 2] =
            *(const float2*)&wb[(size_t)(gt * 256 + uch * 32 + uw) * 256 + cc * 2];
    }

    float creg = 0.f;
    float* ob = layer ? g_out1 : g_out0;
    const int kbase = wg * 64;

    // prefetch xg for t = 0
    float xg[4];
    {
        int td0 = dir ? 255 : 0;
        size_t xb = ((size_t)b_e * 256 + td0) * 2048 + dir * 1024 + uu_e;
        xg[0] = __ldcg(&g_xg[xb]);
        xg[1] = __ldcg(&g_xg[xb + 256]);
        xg[2] = __ldcg(&g_xg[xb + 512]);
        xg[3] = __ldcg(&g_xg[xb + 768]);
    }

    for (int t = 0; t < 256; ++t) {
        int td = dir ? 255 - t : t;
        const float* hin = g_h + (t & 1) * (2 * 128 * 256);
        float* hout = g_h + ((t & 1) ^ 1) * (2 * 128 * 256);

        // stage h_{t-1}: 16 batches x 256 k = 2048 float2, 4 per thread (.cg)
        const float* hb = hin + (dir * 128 + bch * 16) * 256;
#pragma unroll
        for (int r = 0; r < 4; ++r) {
            int q = r * 512 + tid;
            int row = q >> 7, cc = q & 127;
            *(float2*)&hs[row * 258 + cc * 2] = __ldcg((const float2*)&hb[row * 256 + cc * 2]);
        }
        __syncthreads();

        ULL acc[4][4] = {};
#pragma unroll 8
        for (int kp = 0; kp < 32; ++kp) {
            ULL hv[4], wv[4];
#pragma unroll
            for (int j = 0; j < 4; ++j)
                hv[j] = *(const ULL*)&hs[(bg * 4 + j) * 258 + kbase + kp * 2];
#pragma unroll
            for (int g = 0; g < 4; ++g)
                wv[g] = *(const ULL*)&ws[(g * 32 + u) * 258 + kbase + kp * 2];
#pragma unroll
            for (int g = 0; g < 4; ++g)
#pragma unroll
                for (int j = 0; j < 4; ++j) fma2(acc[g][j], hv[j], wv[g]);
        }

        // all wgs publish partials
        {
            ULL* pp = &part[(wg * 128 + wtid) * 17];
#pragma unroll
            for (int g = 0; g < 4; ++g)
#pragma unroll
                for (int j = 0; j < 4; ++j) pp[g * 4 + j] = acc[g][j];
        }
        __syncthreads();

        // distributed epilogue: one cell per thread
        float hn;
        {
            float gv[4];
#pragma unroll
            for (int g = 0; g < 4; ++g) {
                ULL s = part[src * 17 + g * 4 + jj];
#pragma unroll
                for (int w = 1; w < 4; ++w)
                    s = f2add(s, part[(w * 128 + src) * 17 + g * 4 + jj]);
                gv[g] = f2sum(s) + xg[g];
            }
            float cn = sigf(gv[1]) * creg + sigf(gv[0]) * tanhf(gv[2]);
            hn = sigf(gv[3]) * tanhf(cn);
            creg = cn;
            hout[(dir * 128 + b_e) * 256 + uu_e] = hn;
        }
        __syncthreads();

        // release-arrive; hide ob store + next xg prefetch inside the wait
        if (tid == 0) bar_arrive_rel(&g_bar[grp]);
        ob[((size_t)b_e * 256 + td) * 512 + dir * 256 + uu_e] = hn;
        if (t + 1 < 256) {
            int td2 = dir ? 255 - (t + 1) : t + 1;
            size_t xb = ((size_t)b_e * 256 + td2) * 2048 + dir * 1024 + uu_e;
            xg[0] = __ldcg(&g_xg[xb]);
            xg[1] = __ldcg(&g_xg[xb + 256]);
            xg[2] = __ldcg(&g_xg[xb + 512]);
            xg[3] = __ldcg(&g_xg[xb + 768]);
        }
        if (tid == 0) {
            unsigned tgt = 8u * (unsigned)(t + 1);
            while (bar_ld_acq(&g_bar[grp]) < tgt) { }
        }
        __syncthreads();
    }
}

// ---------------- LayerNorm + output projection -------------------------------
__global__ void __launch_bounds__(128) lnfeats(const float* __restrict__ lng,
                                               const float* __restrict__ lnb,
                                               const float* __restrict__ wo,
                                               const float* __restrict__ bo) {
    __shared__ float row[512];
    __shared__ float red[10];
    int i = blockIdx.x, tid = threadIdx.x;
    float4 v = *(const float4*)&g_out1[(size_t)i * 512 + tid * 4];
    float s = v.x + v.y + v.z + v.w;
    float q = v.x * v.x + v.y * v.y + v.z * v.z + v.w * v.w;
#pragma unroll
    for (int o = 16; o; o >>= 1) {
        s += __shfl_xor_sync(0xffffffffu, s, o);
        q += __shfl_xor_sync(0xffffffffu, q, o);
    }
    int wid = tid >> 5, lane = tid & 31;
    if (!lane) { red[wid] = s; red[4 + wid] = q; }
    __syncthreads();
    if (!tid) {
        float S = red[0] + red[1] + red[2] + red[3];
        float Q = red[4] + red[5] + red[6] + red[7];
        float mu = S / 512.f;
        float var = Q / 512.f - mu * mu;
        red[8] = mu;
        red[9] = rsqrtf(var + 1e-5f);
    }
    __syncthreads();
    float mu = red[8], rs = red[9];
    int k = tid * 4;
    row[k + 0] = (v.x - mu) * rs * lng[k + 0] + lnb[k + 0];
    row[k + 1] = (v.y - mu) * rs * lng[k + 1] + lnb[k + 1];
    row[k + 2] = (v.z - mu) * rs * lng[k + 2] + lnb[k + 2];
    row[k + 3] = (v.w - mu) * rs * lng[k + 3] + lnb[k + 3];
    __syncthreads();
    for (int o = wid; o < 22; o += 4) {
        float a = 0.f;
        const float* wr = wo + o * 512;
        for (int k2 = lane; k2 < 512; k2 += 32) a += row[k2] * wr[k2];
#pragma unroll
        for (int off = 16; off; off >>= 1) a += __shfl_xor_sync(0xffffffffu, a, off);
        if (!lane) g_feats[(size_t)i * 22 + o] = a + bo[o];
    }
}

// ---------------- CRF forward + scores (one warp per batch) -------------------
__global__ void crf_k(const float* __restrict__ trans, const int* __restrict__ mask,
                      const int* __restrict__ tags) {
    __shared__ float tr[484];
    __shared__ float alpha[22];
    int b = blockIdx.x, j = threadIdx.x;
    for (int q = j; q < 484; q += 32) tr[q] = trans[q];
    const float* Fb = g_feats + (size_t)b * 256 * 22;
    __syncwarp();
    if (j < 22) alpha[j] = tr[20 * 22 + j] + Fb[j];
    __syncwarp();
    for (int t = 1; t < 256; ++t) {
        float aj = 0.f;
        if (j < 22) {
            float m = -1e30f;
#pragma unroll
            for (int i2 = 0; i2 < 22; ++i2) m = fmaxf(m, alpha[i2] + tr[i2 * 22 + j]);
            float sm = 0.f;
#pragma unroll
            for (int i2 = 0; i2 < 22; ++i2) sm += expf(alpha[i2] + tr[i2 * 22 + j] - m);
            aj = m + logf(sm) + Fb[t * 22 + j];
        }
        int mt = mask[b * 256 + t];
        __syncwarp();
        if (j < 22 && mt) alpha[j] = aj;
        __syncwarp();
    }
    float v = (j < 22) ? alpha[j] + tr[j * 22 + 21] : -1e30f;
    float m = v;
#pragma unroll
    for (int off = 16; off; off >>= 1) m = fmaxf(m, __shfl_xor_sync(0xffffffffu, m, off));
    float e = (j < 22) ? expf(v - m) : 0.f;
#pragma unroll
    for (int off = 16; off; off >>= 1) e += __shfl_xor_sync(0xffffffffu, e, off);
    float logZ = m + logf(e);

    const int* tg = tags + (size_t)b * 256;
    const int* mk = mask + b * 256;
    float emit = 0.f, trs = 0.f;
    int cnt = 0;
    for (int t = j; t < 256; t += 32) {
        if (mk[t]) {
            emit += Fb[t * 22 + tg[t]];
            cnt++;
            if (t >= 1) trs += tr[tg[t - 1] * 22 + tg[t]];
        }
    }
#pragma unroll
    for (int off = 16; off; off >>= 1) {
        emit += __shfl_xor_sync(0xffffffffu, emit, off);
        trs += __shfl_xor_sync(0xffffffffu, trs, off);
        cnt += __shfl_xor_sync(0xffffffffu, cnt, off);
    }
    if (!j) {
        trs += tr[20 * 22 + tg[0]];
        trs += tr[tg[cnt - 1] * 22 + 21];
        g_nll[b] = logZ - emit - trs;
    }
}

__global__ void reduce_nll(float* out) {
    int tid = threadIdx.x;
    float v = g_nll[tid];
#pragma unroll
    for (int off = 16; off; off >>= 1) v += __shfl_xor_sync(0xffffffffu, v, off);
    __shared__ float r[4];
    if (!(tid & 31)) r[tid >> 5] = v;
    __syncthreads();
    if (!tid) out[0] = (r[0] + r[1] + r[2] + r[3]) / 128.f;
}

// ---------------- launcher ----------------
extern "C" void kernel_launch(void* const* d_in, const int* in_sizes, int n_in,
                              void* d_out, int out_size) {
    const float* emb    = (const float*)d_in[0];
    const float* w_ih0  = (const float*)d_in[1];
    const float* w_hh0  = (const float*)d_in[2];
    const float* b_ih0  = (const float*)d_in[3];
    const float* b_hh0  = (const float*)d_in[4];
    const float* w_ih1  = (const float*)d_in[5];
    const float* w_hh1  = (const float*)d_in[6];
    const float* b_ih1  = (const float*)d_in[7];
    const float* b_hh1  = (const float*)d_in[8];
    const float* ln_g   = (const float*)d_in[9];
    const float* ln_b   = (const float*)d_in[10];
    const float* w_out  = (const float*)d_in[11];
    const float* b_out  = (const float*)d_in[12];
    const float* trans  = (const float*)d_in[13];
    const int* words    = (const int*)d_in[14];
    const int* mask     = (const int*)d_in[15];
    const int* tags     = (const int*)d_in[16];
    float* out = (float*)d_out;

    cudaFuncSetAttribute(lstm_persist, cudaFuncAttributeMaxDynamicSharedMemorySize, PERS_SMEM);
    cudaFuncSetAttribute(gemm_tc<256>, cudaFuncAttributeMaxDynamicSharedMemorySize, GT_SMEM);
    cudaFuncSetAttribute(gemm_tc<512>, cudaFuncAttributeMaxDynamicSharedMemorySize, GT_SMEM);

    // layer 0
    embed_bf<<<32768, 256>>>(emb, words);
    conv_w<<<2048, 256>>>(w_ih0);
    gemm_tc<256><<<dim3(16, 256), 256, GT_SMEM>>>(b_ih0, b_hh0);
    init_hc<<<512, 256>>>();
    lstm_persist<<<128, 512, PERS_SMEM>>>(w_hh0, 0);
    // layer 1
    conv_a1<<<65536, 256>>>();
    conv_w<<<4096, 256>>>(w_ih1);
    gemm_tc<512><<<dim3(16, 256), 256, GT_SMEM>>>(b_ih1, b_hh1);
    init_hc<<<512, 256>>>();
    lstm_persist<<<128, 512, PERS_SMEM>>>(w_hh1, 1);
    // head
    lnfeats<<<32768, 128>>>(ln_g, ln_b, w_out, b_out);
    crf_k<<<128, 32>>>(trans, mask, tags);
    reduce_nll<<<1, 128>>>(out);
}

// round 12
// speedup vs baseline: 2.5910x; 1.0050x over previous
#include <cuda_runtime.h>
#include <cuda_bf16.h>
#include <cstdint>

typedef unsigned long long ULL;

// tcgen05 is an arch-SPECIFIC feature: legal in the sm_103a cubin pass,
// illegal in the generic compute_103 PTX pass the harness also emits.
#if !defined(__CUDA_ARCH__) || defined(__CUDA_ARCH_FEAT_SM103_ALL) || \
    defined(__CUDA_ARCH_FEAT_SM100_ALL) || defined(__CUDA_ARCH_SPECIFIC__) || \
    defined(__CUDA_ARCH_FAMILY_SPECIFIC__)
#define TC_OK 1
#else
#define TC_OK 0
#endif

// ---------------- f32x2 helpers (recurrence) ----------------
__device__ __forceinline__ void fma2(ULL& d, ULL a, ULL b) {
    asm("fma.rn.f32x2 %0, %1, %2, %0;" : "+l"(d) : "l"(a), "l"(b));
}
__device__ __forceinline__ ULL f2add(ULL a, ULL b) {
    ULL d;
    asm("add.rn.f32x2 %0, %1, %2;" : "=l"(d) : "l"(a), "l"(b));
    return d;
}
__device__ __forceinline__ float f2sum(ULL v) {
    float x, y;
    asm("mov.b64 {%0,%1}, %2;" : "=f"(x), "=f"(y) : "l"(v));
    return x + y;
}
__device__ __forceinline__ float sigf(float x) { return 1.f / (1.f + expf(-x)); }

// ---------------- tcgen05 helpers (guarded) ----------------
__device__ __forceinline__ uint32_t smem_u32(const void* p) {
    uint32_t a;
    asm("{ .reg .u64 t; cvta.to.shared.u64 t, %1; cvt.u32.u64 %0, t; }" : "=r"(a) : "l"(p));
    return a;
}
#define SW128(o) ((o) ^ (((o) >> 3) & 0x70))
static constexpr uint64_t DESC_BASE_SW128 =
    (uint64_t(2) << 61) | (uint64_t(1) << 46) | (uint64_t(64) << 32) | (uint64_t(1) << 16);
#define MKDESC(a) (DESC_BASE_SW128 | ((uint64_t)((a) >> 4) & 0x3FFF))

#if TC_OK
__device__ __forceinline__ uint32_t elect1() {
    uint32_t p;
    asm volatile("{\n\t.reg .pred p;\n\telect.sync _|p, 0xFFFFFFFF;\n\tselp.b32 %0, 1, 0, p;\n\t}" : "=r"(p));
    return p;
}
#define MBAR_INIT(m, c) asm volatile("mbarrier.init.shared.b64 [%0], %1;" :: "r"(m), "r"(c) : "memory")
#define MBAR_INVAL(m) asm volatile("mbarrier.inval.shared.b64 [%0];" :: "r"(m) : "memory")
#define MBAR_WAIT(m, ph) do { \
    uint32_t _m = (m), _p = (ph), _d; \
    asm volatile("{\n\t.reg .pred p;\n\tmbarrier.try_wait.parity.acquire.cta.shared::cta.b64 p, [%1], %2;\n\tselp.b32 %0,1,0,p;\n\t}" \
        : "=r"(_d) : "r"(_m), "r"(_p) : "memory"); \
    if (!_d) { asm volatile("{\n\t.reg .pred P1;\n\tWL%=:\n\tmbarrier.try_wait.parity.acquire.cta.shared::cta.b64 P1, [%0], %1, 0x989680;\n\t@P1 bra.uni WD%=;\n\tbra.uni WL%=;\n\tWD%=:\n\t}" :: "r"(_m), "r"(_p) : "memory"); } \
} while (0)
#define TC_ALLOC(sa, n)  asm volatile("tcgen05.alloc.cta_group::1.sync.aligned.shared::cta.b32 [%0], %1;" :: "r"(sa), "r"(n) : "memory")
#define TC_RELINQ()      asm volatile("tcgen05.relinquish_alloc_permit.cta_group::1.sync.aligned;")
#define TC_DEALLOC(t, n) asm volatile("tcgen05.dealloc.cta_group::1.sync.aligned.b32 %0, %1;" :: "r"(t), "r"(n))
#define TC_COMMIT(m)     asm volatile("tcgen05.commit.cta_group::1.mbarrier::arrive::one.shared::cluster.b64 [%0];" :: "r"(m) : "memory")
#define TC_WAIT_LD()     asm volatile("tcgen05.wait::ld.sync.aligned;" ::: "memory")
#define TC_FENCE_AFTER() asm volatile("tcgen05.fence::after_thread_sync;" ::: "memory")
#define TC_FENCE_BEFORE() asm volatile("tcgen05.fence::before_thread_sync;" ::: "memory")
#define FENCE_ASYNC()    asm volatile("fence.proxy.async.shared::cta;" ::: "memory")
#define TC_LD_X32(r, a) \
    asm volatile("tcgen05.ld.sync.aligned.32x32b.x32.b32 " \
        "{%0,%1,%2,%3,%4,%5,%6,%7,%8,%9,%10,%11,%12,%13,%14,%15," \
        "%16,%17,%18,%19,%20,%21,%22,%23,%24,%25,%26,%27,%28,%29,%30,%31}, [%32];" \
        : "=r"((r)[0]),"=r"((r)[1]),"=r"((r)[2]),"=r"((r)[3]),"=r"((r)[4]),"=r"((r)[5]),"=r"((r)[6]),"=r"((r)[7]), \
          "=r"((r)[8]),"=r"((r)[9]),"=r"((r)[10]),"=r"((r)[11]),"=r"((r)[12]),"=r"((r)[13]),"=r"((r)[14]),"=r"((r)[15]), \
          "=r"((r)[16]),"=r"((r)[17]),"=r"((r)[18]),"=r"((r)[19]),"=r"((r)[20]),"=r"((r)[21]),"=r"((r)[22]),"=r"((r)[23]), \
          "=r"((r)[24]),"=r"((r)[25]),"=r"((r)[26]),"=r"((r)[27]),"=r"((r)[28]),"=r"((r)[29]),"=r"((r)[30]),"=r"((r)[31]) \
        : "r"(a))
__device__ __forceinline__ void mma_f16_ss(uint32_t d, uint64_t ad, uint64_t bd, uint32_t idesc, uint32_t en) {
    asm volatile(
        "{\n\t.reg .pred p;\n\tsetp.ne.u32 p, %5, 0;\n\t"
        "tcgen05.mma.cta_group::1.kind::f16 [%0], %1, %2, %3, {%4, %4, %4, %4}, p;\n\t}"
        :: "r"(d), "l"(ad), "l"(bd), "r"(idesc), "r"(0u), "r"(en) : "memory");
}
#endif // TC_OK

// M=128, N=128, bf16 x bf16 -> f32
static constexpr uint32_t GEMM_IDESC = (1u << 4) | (1u << 7) | (1u << 10) | (16u << 17) | (8u << 24);

// ---------------- scratch ----------------
__device__ __nv_bfloat16 g_Ah[(size_t)32768 * 512];
__device__ __nv_bfloat16 g_Al[(size_t)32768 * 512];
__device__ __nv_bfloat16 g_Wh[2048 * 512];
__device__ __nv_bfloat16 g_Wl[2048 * 512];
__device__ float g_xg[(size_t)32768 * 2048];
__device__ float g_out1[32768 * 512];
__device__ float g_h[2 * 2 * 128 * 256];
__device__ float g_feats[(size_t)32768 * 22];
__device__ float g_nll[128];
__device__ unsigned g_bar[16];

// ---------------- release/acquire barrier primitives ----------------
__device__ __forceinline__ void bar_arrive_rel(unsigned* p) {
    asm volatile("red.release.gpu.global.add.u32 [%0], %1;" :: "l"(p), "r"(1u) : "memory");
}
__device__ __forceinline__ unsigned bar_ld_acq(unsigned* p) {
    unsigned v;
    asm volatile("ld.acquire.gpu.global.u32 %0, [%1];" : "=r"(v) : "l"(p) : "memory");
    return v;
}

// ---------------- embedding gather -> bf16 hi/lo (layer0 A, stride 256) ------
__global__ void embed_bf(const float* __restrict__ emb, const int* __restrict__ words) {
    int idx = blockIdx.x * 256 + threadIdx.x;
    int i = idx >> 8, e = idx & 255;
    float x = emb[(size_t)words[i] * 256 + e];
    __nv_bfloat16 h = __float2bfloat16_rn(x);
    g_Ah[idx] = h;
    g_Al[idx] = __float2bfloat16_rn(x - __bfloat162float(h));
}

// ---------------- fp32 -> bf16 hi/lo weight converter ----------------
__global__ void conv_w(const float* __restrict__ W) {
    size_t idx = (size_t)blockIdx.x * 256 + threadIdx.x;
    float x = W[idx];
    __nv_bfloat16 h = __float2bfloat16_rn(x);
    g_Wh[idx] = h;
    g_Wl[idx] = __float2bfloat16_rn(x - __bfloat162float(h));
}

// ---------------- tcgen05 input-projection GEMM (round-9, passing) ------------
#define GT_SMEM (1024 + 4 * 16384)
template <int K>
__global__ void __launch_bounds__(256, 2)
gemm_tc(const float* __restrict__ bi, const float* __restrict__ bh) {
#if TC_OK
    extern __shared__ char smx[];
    uint32_t sb = smem_u32(smx);
    const int SM_TM = 0, SM_MB = 8;
    const int SM_AH = 1024, SM_AL = SM_AH + 16384, SM_WH = SM_AL + 16384, SM_WL = SM_WH + 16384;

    int tid = threadIdx.x, wid = tid >> 5, lid = tid & 31;
    int nt = blockIdx.x, mt = blockIdx.y;

    if (wid == 0) {
        TC_ALLOC(sb + SM_TM, 128);
        TC_RELINQ();
    }
    if (tid == 0) MBAR_INIT(sb + SM_MB, 1);
    __syncthreads();
    uint32_t tmem;
    asm volatile("ld.shared.b32 %0, [%1];" : "=r"(tmem) : "r"(sb + SM_TM));

    const int NC = K / 64;
    for (int ci = 0; ci < NC; ++ci) {
#pragma unroll
        for (int i = 0; i < 4; ++i) {
            int idx = i * 256 + tid;
            int r = idx >> 3, c8 = idx & 7;
            uint32_t so = SW128((uint32_t)(r * 128 + c8 * 16));
            size_t ga = (size_t)(mt * 128 + r) * K + ci * 64 + c8 * 8;
            *(uint4*)(smx + SM_AH + so) = *(const uint4*)(g_Ah + ga);
            *(uint4*)(smx + SM_AL + so) = *(const uint4*)(g_Al + ga);
            size_t gw = (size_t)(nt * 128 + r) * K + ci * 64 + c8 * 8;
            *(uint4*)(smx + SM_WH + so) = *(const uint4*)(g_Wh + gw);
            *(uint4*)(smx + SM_WL + so) = *(const uint4*)(g_Wl + gw);
        }
        FENCE_ASYNC();
        __syncthreads();

        if (wid == 0 && elect1()) {
            uint64_t dAh = MKDESC(sb + SM_AH), dAl = MKDESC(sb + SM_AL);
            uint64_t dWh = MKDESC(sb + SM_WH), dWl = MKDESC(sb + SM_WL);
#pragma unroll
            for (int k = 0; k < 4; ++k) {
                uint64_t o = k * 2;
                mma_f16_ss(tmem, dAh + o, dWh + o, GEMM_IDESC, !(ci == 0 && k == 0));
                mma_f16_ss(tmem, dAh + o, dWl + o, GEMM_IDESC, 1u);
                mma_f16_ss(tmem, dAl + o, dWh + o, GEMM_IDESC, 1u);
            }
            TC_COMMIT(sb + SM_MB);
        }
        MBAR_WAIT(sb + SM_MB, (uint32_t)(ci & 1));
        __syncthreads();
    }

    TC_FENCE_AFTER();
    if (wid < 4) {
        int m = mt * 128 + wid * 32 + lid;
#pragma unroll
        for (int nb = 0; nb < 4; ++nb) {
            uint32_t dr[32];
            TC_LD_X32(dr, tmem + nb * 32);
            TC_WAIT_LD();
            int n0 = nt * 128 + nb * 32;
#pragma unroll
            for (int c8 = 0; c8 < 8; ++c8) {
                float4 o;
                int n = n0 + c8 * 4;
                o.x = __uint_as_float(dr[c8 * 4 + 0]) + bi[n + 0] + bh[n + 0];
                o.y = __uint_as_float(dr[c8 * 4 + 1]) + bi[n + 1] + bh[n + 1];
                o.z = __uint_as_float(dr[c8 * 4 + 2]) + bi[n + 2] + bh[n + 2];
                o.w = __uint_as_float(dr[c8 * 4 + 3]) + bi[n + 3] + bh[n + 3];
                *(float4*)&g_xg[(size_t)m * 2048 + n] = o;
            }
        }
    }
    TC_FENCE_BEFORE();
    __syncthreads();
    if (tid == 0) MBAR_INVAL(sb + SM_MB);
    if (wid == 0) TC_DEALLOC(tmem, 128);
#else
    // Correct SIMT fallback for the generic compute_103 PTX pass (never runs).
    int tid = threadIdx.x;
    int nt = blockIdx.x, mt = blockIdx.y;
    for (int q = tid; q < 128 * 128; q += 256) {
        int mi = q >> 7, ni = q & 127;
        int m = mt * 128 + mi, n = nt * 128 + ni;
        float s = 0.f;
        for (int k = 0; k < K; ++k) {
            float a = __bfloat162float(g_Ah[(size_t)m * K + k]) + __bfloat162float(g_Al[(size_t)m * K + k]);
            float w = __bfloat162float(g_Wh[(size_t)n * K + k]) + __bfloat162float(g_Wl[(size_t)n * K + k]);
            s += a * w;
        }
        g_xg[(size_t)m * 2048 + n] = s + bi[n] + bh[n];
    }
#endif
}

// ---------------- zero h pings + group barriers ----------------
__global__ void init_hc() {
    int i = blockIdx.x * 256 + threadIdx.x;   // 128 blocks: 32768 float4
    *(float4*)&g_h[i * 4] = make_float4(0.f, 0.f, 0.f, 0.f);
    if (i < 16) g_bar[i] = 0u;
}

// ---------------- persistent BiLSTM layer v7 ----------------------------------
// 128 blocks: bx bit0 = dir, bits1-3 = bch (8 groups of 16 batches),
// bits4-6 = uch (8 chunks of 32 units). Barrier group = (dir,bch) -> 8 blocks.
// 512 threads: wg = tid>>7 splits K 4 ways; wtid = tid&127: u = wtid&31 (unit),
// bg = wtid>>5 (4 groups x 4 batches). Row stride 260 floats (16B aligned) ->
// MMA loop uses LDS.128 (conflict-free per 8-lane phase). Layer 0 writes its
// output directly as bf16 hi/lo into g_Ah/g_Al (fuses away the convert kernel).
#define PERS_SMEM ((128 * 260 + 16 * 260) * 4 + 4 * 128 * 17 * 8)
__global__ void __launch_bounds__(512) lstm_persist(const float* __restrict__ whh, int layer) {
    extern __shared__ float sm[];
    float* ws = sm;                        // [128][260] rows: g*32 + u
    float* hs = sm + 128 * 260;            // [16][260]
    ULL* part = (ULL*)(sm + 144 * 260);    // [4][128][17]

    int bx = blockIdx.x;
    int dir = bx & 1, bch = (bx >> 1) & 7, uch = bx >> 4;
    int grp = bx & 15;
    int tid = threadIdx.x;
    int wg = tid >> 7, wtid = tid & 127;
    int u = wtid & 31, bg = wtid >> 5;

    // epilogue cell: one (batch, unit) per thread
    int u_l = tid & 31, b_l = tid >> 5;            // u_l 0..31, b_l 0..15
    int uu_e = uch * 32 + u_l;
    int b_e = bch * 16 + b_l;
    int src = (b_l >> 2) * 32 + u_l;               // producing wtid
    int jj = b_l & 3;                              // j within producer

    // stage W_hh slice once: 128 rows (4 gates x 32 units) x 256 k = 16384 float2
    const float* wb = whh + (size_t)dir * 1024 * 256;
#pragma unroll 4
    for (int r = 0; r < 32; ++r) {
        int q = r * 512 + tid;
        int wrow = q >> 7, cc = q & 127;
        int gt = wrow >> 5, uw = wrow & 31;
        *(float2*)&ws[wrow * 260 + cc * 2] =
            *(const float2*)&wb[(size_t)(gt * 256 + uch * 32 + uw) * 256 + cc * 2];
    }

    float creg = 0.f;
    const int kbase = wg * 64;

    // prefetch xg for t = 0
    float xg[4];
    {
        int td0 = dir ? 255 : 0;
        size_t xb = ((size_t)b_e * 256 + td0) * 2048 + dir * 1024 + uu_e;
        xg[0] = __ldcg(&g_xg[xb]);
        xg[1] = __ldcg(&g_xg[xb + 256]);
        xg[2] = __ldcg(&g_xg[xb + 512]);
        xg[3] = __ldcg(&g_xg[xb + 768]);
    }

    for (int t = 0; t < 256; ++t) {
        int td = dir ? 255 - t : t;
        const float* hin = g_h + (t & 1) * (2 * 128 * 256);
        float* hout = g_h + ((t & 1) ^ 1) * (2 * 128 * 256);

        // stage h_{t-1}: 16 batches x 256 k = 2048 float2, 4 per thread (.cg)
        const float* hb = hin + (dir * 128 + bch * 16) * 256;
#pragma unroll
        for (int r = 0; r < 4; ++r) {
            int q = r * 512 + tid;
            int row = q >> 7, cc = q & 127;
            *(float2*)&hs[row * 260 + cc * 2] = __ldcg((const float2*)&hb[row * 256 + cc * 2]);
        }
        __syncthreads();

        // MMA: LDS.128 (4 k-floats per load)
        ULL acc[4][4] = {};
#pragma unroll
        for (int kq = 0; kq < 16; ++kq) {
            ulonglong2 hv[4], wv[4];
#pragma unroll
            for (int j = 0; j < 4; ++j)
                hv[j] = *(const ulonglong2*)&hs[(bg * 4 + j) * 260 + kbase + kq * 4];
#pragma unroll
            for (int g = 0; g < 4; ++g)
                wv[g] = *(const ulonglong2*)&ws[(g * 32 + u) * 260 + kbase + kq * 4];
#pragma unroll
            for (int g = 0; g < 4; ++g)
#pragma unroll
                for (int j = 0; j < 4; ++j) {
                    fma2(acc[g][j], hv[j].x, wv[g].x);
                    fma2(acc[g][j], hv[j].y, wv[g].y);
                }
        }

        // all wgs publish partials
        {
            ULL* pp = &part[(wg * 128 + wtid) * 17];
#pragma unroll
            for (int g = 0; g < 4; ++g)
#pragma unroll
                for (int j = 0; j < 4; ++j) pp[g * 4 + j] = acc[g][j];
        }
        __syncthreads();

        // distributed epilogue: one cell per thread
        float hn;
        {
            float gv[4];
#pragma unroll
            for (int g = 0; g < 4; ++g) {
                ULL s = part[src * 17 + g * 4 + jj];
#pragma unroll
                for (int w = 1; w < 4; ++w)
                    s = f2add(s, part[(w * 128 + src) * 17 + g * 4 + jj]);
                gv[g] = f2sum(s) + xg[g];
            }
            float cn = sigf(gv[1]) * creg + sigf(gv[0]) * tanhf(gv[2]);
            hn = sigf(gv[3]) * tanhf(cn);
            creg = cn;
            hout[(dir * 128 + b_e) * 256 + uu_e] = hn;
        }
        __syncthreads();

        // release-arrive; hide output store + next xg prefetch inside the wait
        if (tid == 0) bar_arrive_rel(&g_bar[grp]);
        {
            size_t oi = ((size_t)b_e * 256 + td) * 512 + dir * 256 + uu_e;
            if (layer == 0) {
                __nv_bfloat16 hh = __float2bfloat16_rn(hn);
                g_Ah[oi] = hh;
                g_Al[oi] = __float2bfloat16_rn(hn - __bfloat162float(hh));
            } else {
                g_out1[oi] = hn;
            }
        }
        if (t + 1 < 256) {
            int td2 = dir ? 255 - (t + 1) : t + 1;
            size_t xb = ((size_t)b_e * 256 + td2) * 2048 + dir * 1024 + uu_e;
            xg[0] = __ldcg(&g_xg[xb]);
            xg[1] = __ldcg(&g_xg[xb + 256]);
            xg[2] = __ldcg(&g_xg[xb + 512]);
            xg[3] = __ldcg(&g_xg[xb + 768]);
        }
        if (tid == 0) {
            unsigned tgt = 8u * (unsigned)(t + 1);
            while (bar_ld_acq(&g_bar[grp]) < tgt) { }
        }
        __syncthreads();
    }
}

// ---------------- LayerNorm + output projection (16 tokens/block) -------------
// w_out staged in smem once per block -> L2 traffic for w_out /16.
// 256 threads = 2 token-groups of 128; 8 iterations of 2 tokens.
#define LN_SMEM (22 * 512 * 4 + 2 * 512 * 4 + 2 * 16 * 4 + 32 * 4)
__global__ void __launch_bounds__(256) lnfeats16(const float* __restrict__ lng,
                                                 const float* __restrict__ lnb,
                                                 const float* __restrict__ wo,
                                                 const float* __restrict__ bo) {
    extern __shared__ float lsm[];
    float* wos = lsm;                 // [22][512]
    float* row = lsm + 22 * 512;      // [2][512]
    float* red = row + 2 * 512;       // [2][16]
    float* bos = red + 2 * 16;        // [32]

    int tid = threadIdx.x;
    for (int q = tid; q < 22 * 512; q += 256) wos[q] = wo[q];
    if (tid < 22) bos[tid] = bo[tid];
    __syncthreads();

    int half = tid >> 7, t128 = tid & 127;
    int wid = t128 >> 5, lane = t128 & 31;

    for (int it = 0; it < 8; ++it) {
        int i = blockIdx.x * 16 + it * 2 + half;
        float4 v = *(const float4*)&g_out1[(size_t)i * 512 + t128 * 4];
        float s = v.x + v.y + v.z + v.w;
        float q = v.x * v.x + v.y * v.y + v.z * v.z + v.w * v.w;
#pragma unroll
        for (int o = 16; o; o >>= 1) {
            s += __shfl_xor_sync(0xffffffffu, s, o);
            q += __shfl_xor_sync(0xffffffffu, q, o);
        }
        if (!lane) { red[half * 16 + wid] = s; red[half * 16 + 4 + wid] = q; }
        __syncthreads();
        if (t128 == 0) {
            float S = red[half * 16 + 0] + red[half * 16 + 1] + red[half * 16 + 2] + red[half * 16 + 3];
            float Q = red[half * 16 + 4] + red[half * 16 + 5] + red[half * 16 + 6] + red[half * 16 + 7];
            float mu = S / 512.f;
            float var = Q / 512.f - mu * mu;
            red[half * 16 + 8] = mu;
            red[half * 16 + 9] = rsqrtf(var + 1e-5f);
        }
        __syncthreads();
        float mu = red[half * 16 + 8], rs = red[half * 16 + 9];
        int k = t128 * 4;
        float* rw = &row[half * 512];
        rw[k + 0] = (v.x - mu) * rs * lng[k + 0] + lnb[k + 0];
        rw[k + 1] = (v.y - mu) * rs * lng[k + 1] + lnb[k + 1];
        rw[k + 2] = (v.z - mu) * rs * lng[k + 2] + lnb[k + 2];
        rw[k + 3] = (v.w - mu) * rs * lng[k + 3] + lnb[k + 3];
        __syncthreads();
        for (int o = wid; o < 22; o += 4) {
            float a = 0.f;
            const float* wr = &wos[o * 512];
            for (int k2 = lane; k2 < 512; k2 += 32) a += rw[k2] * wr[k2];
#pragma unroll
            for (int off = 16; off; off >>= 1) a += __shfl_xor_sync(0xffffffffu, a, off);
            if (!lane) g_feats[(size_t)i * 22 + o] = a + bos[o];
        }
        __syncthreads();
    }
}

// ---------------- CRF forward + scores (one warp per batch) -------------------
__global__ void crf_k(const float* __restrict__ trans, const int* __restrict__ mask,
                      const int* __restrict__ tags) {
    __shared__ float tr[484];
    __shared__ float alpha[22];
    int b = blockIdx.x, j = threadIdx.x;
    for (int q = j; q < 484; q += 32) tr[q] = trans[q];
    const float* Fb = g_feats + (size_t)b * 256 * 22;
    __syncwarp();
    if (j < 22) alpha[j] = tr[20 * 22 + j] + Fb[j];
    __syncwarp();
    for (int t = 1; t < 256; ++t) {
        float aj = 0.f;
        if (j < 22) {
            float m = -1e30f;
#pragma unroll
            for (int i2 = 0; i2 < 22; ++i2) m = fmaxf(m, alpha[i2] + tr[i2 * 22 + j]);
            float sm = 0.f;
#pragma unroll
            for (int i2 = 0; i2 < 22; ++i2) sm += expf(alpha[i2] + tr[i2 * 22 + j] - m);
            aj = m + logf(sm) + Fb[t * 22 + j];
        }
        int mt = mask[b * 256 + t];
        __syncwarp();
        if (j < 22 && mt) alpha[j] = aj;
        __syncwarp();
    }
    float v = (j < 22) ? alpha[j] + tr[j * 22 + 21] : -1e30f;
    float m = v;
#pragma unroll
    for (int off = 16; off; off >>= 1) m = fmaxf(m, __shfl_xor_sync(0xffffffffu, m, off));
    float e = (j < 22) ? expf(v - m) : 0.f;
#pragma unroll
    for (int off = 16; off; off >>= 1) e += __shfl_xor_sync(0xffffffffu, e, off);
    float logZ = m + logf(e);

    const int* tg = tags + (size_t)b * 256;
    const int* mk = mask + b * 256;
    float emit = 0.f, trs = 0.f;
    int cnt = 0;
    for (int t = j; t < 256; t += 32) {
        if (mk[t]) {
            emit += Fb[t * 22 + tg[t]];
            cnt++;
            if (t >= 1) trs += tr[tg[t - 1] * 22 + tg[t]];
        }
    }
#pragma unroll
    for (int off = 16; off; off >>= 1) {
        emit += __shfl_xor_sync(0xffffffffu, emit, off);
        trs += __shfl_xor_sync(0xffffffffu, trs, off);
        cnt += __shfl_xor_sync(0xffffffffu, cnt, off);
    }
    if (!j) {
        trs += tr[20 * 22 + tg[0]];
        trs += tr[tg[cnt - 1] * 22 + 21];
        g_nll[b] = logZ - emit - trs;
    }
}

__global__ void reduce_nll(float* out) {
    int tid = threadIdx.x;
    float v = g_nll[tid];
#pragma unroll
    for (int off = 16; off; off >>= 1) v += __shfl_xor_sync(0xffffffffu, v, off);
    __shared__ float r[4];
    if (!(tid & 31)) r[tid >> 5] = v;
    __syncthreads();
    if (!tid) out[0] = (r[0] + r[1] + r[2] + r[3]) / 128.f;
}

// ---------------- launcher ----------------
extern "C" void kernel_launch(void* const* d_in, const int* in_sizes, int n_in,
                              void* d_out, int out_size) {
    const float* emb    = (const float*)d_in[0];
    const float* w_ih0  = (const float*)d_in[1];
    const float* w_hh0  = (const float*)d_in[2];
    const float* b_ih0  = (const float*)d_in[3];
    const float* b_hh0  = (const float*)d_in[4];
    const float* w_ih1  = (const float*)d_in[5];
    const float* w_hh1  = (const float*)d_in[6];
    const float* b_ih1  = (const float*)d_in[7];
    const float* b_hh1  = (const float*)d_in[8];
    const float* ln_g   = (const float*)d_in[9];
    const float* ln_b   = (const float*)d_in[10];
    const float* w_out  = (const float*)d_in[11];
    const float* b_out  = (const float*)d_in[12];
    const float* trans  = (const float*)d_in[13];
    const int* words    = (const int*)d_in[14];
    const int* mask     = (const int*)d_in[15];
    const int* tags     = (const int*)d_in[16];
    float* out = (float*)d_out;

    cudaFuncSetAttribute(lstm_persist, cudaFuncAttributeMaxDynamicSharedMemorySize, PERS_SMEM);
    cudaFuncSetAttribute(gemm_tc<256>, cudaFuncAttributeMaxDynamicSharedMemorySize, GT_SMEM);
    cudaFuncSetAttribute(gemm_tc<512>, cudaFuncAttributeMaxDynamicSharedMemorySize, GT_SMEM);
    cudaFuncSetAttribute(lnfeats16, cudaFuncAttributeMaxDynamicSharedMemorySize, LN_SMEM);

    // layer 0
    embed_bf<<<32768, 256>>>(emb, words);
    conv_w<<<2048, 256>>>(w_ih0);
    gemm_tc<256><<<dim3(16, 256), 256, GT_SMEM>>>(b_ih0, b_hh0);
    init_hc<<<128, 256>>>();
    lstm_persist<<<128, 512, PERS_SMEM>>>(w_hh0, 0);   // writes bf16 hi/lo out
    // layer 1
    conv_w<<<4096, 256>>>(w_ih1);
    gemm_tc<512><<<dim3(16, 256), 256, GT_SMEM>>>(b_ih1, b_hh1);
    init_hc<<<128, 256>>>();
    lstm_persist<<<128, 512, PERS_SMEM>>>(w_hh1, 1);
    // head
    lnfeats16<<<2048, 256, LN_SMEM>>>(ln_g, ln_b, w_out, b_out);
    crf_k<<<128, 32>>>(trans, mask, tags);
    reduce_nll<<<1, 128>>>(out);
}